// round 3
// baseline (speedup 1.0000x reference)
#include <cuda_runtime.h>
#include <math.h>
#include <stddef.h>

// Problem constants
#define NN    4096      // nodes
#define TT    16        // timesteps / out features
#define FF    4         // node features
#define HIDC  64        // hidden per head
#define NH    4         // heads
#define NCHUNK 64
#define CHSZ   64       // NN / NCHUNK

// ---------------------------------------------------------------------------
// Scratch (static device global — no runtime allocation, accessed directly
// from kernels; kernel_launch performs kernel launches ONLY)
// ---------------------------------------------------------------------------
struct Scratch {
    // layer 1
    float  Wh[NH * NN * HIDC];        // per-head h@W
    float  s1[NH * NN];
    float  s2[NH * NN];
    float  s2s[NH * NN];              // sorted s2
    int    perm[NH * NN];             // sorted position -> original index
    float  A[NH * NN];                // exp(s2_sorted)
    float  B[NH * NN];                // exp(0.01*s2_sorted)
    double csA[NH * NCHUNK * HIDC];   // chunk sums -> exclusive suffix offsets
    double csB[NH * NCHUNK * HIDC];   // chunk sums -> exclusive prefix offsets
    float  sufA[NH * (NN + 1) * HIDC];
    float  preB[NH * (NN + 1) * HIDC];
    double sufAsc[NH * (NN + 1)];     // scalar suffix sums of A
    double preBsc[NH * (NN + 1)];     // scalar prefix sums of B
    float  hcat[NN * NH * HIDC];      // concatenated head outputs
    // layer 2
    float  Wh2[NN * TT];
    float  s1o[NN], s2o[NN], s2so[NN];
    int    permo[NN];
    float  Ao[NN], Bo[NN];
    double csA2[NCHUNK * TT], csB2[NCHUNK * TT];
    float  sufA2[(NN + 1) * TT], preB2[(NN + 1) * TT];
    double sufA2sc[NN + 1], preB2sc[NN + 1];
};
__device__ Scratch S;

// ---------------------------------------------------------------------------
// Kernel 1: fused transpose(x) -> h, Wh = h @ W[head], s1 = Wh@a1, s2 = Wh@a2
// grid (NN/64, NH), block 256
// ---------------------------------------------------------------------------
__global__ void k_gemm1(const float* __restrict__ x,
                        const float* __restrict__ W,
                        const float* __restrict__ a1,
                        const float* __restrict__ a2)
{
    __shared__ float sW[64 * 65];   // W during compute, reused for Wh tile
    __shared__ float sh[64 * 65];   // h tile (64 rows x 64 feats)

    const int head = blockIdx.y;
    const int n0   = blockIdx.x * 64;
    const int t    = threadIdx.x;

    // load W[head] (64x64, row-major [in][out])
    const float* Wp = W + head * 64 * 64;
    for (int idx = t; idx < 4096; idx += 256)
        sW[(idx >> 6) * 65 + (idx & 63)] = Wp[idx];

    // load h rows n0..n0+63: h[n][t16*4+f] = x[t16, n, f]
    {
        const int dn = t >> 2, f = t & 3;
        #pragma unroll
        for (int tt = 0; tt < TT; tt++)
            sh[dn * 65 + tt * 4 + f] = x[(size_t)tt * NN * FF + (size_t)(n0 + dn) * FF + f];
    }
    __syncthreads();

    const int tc = t & 15, tr = t >> 4;   // 16x16 threads, 4x4 register tile each
    float acc[4][4];
    #pragma unroll
    for (int i = 0; i < 4; i++)
        #pragma unroll
        for (int j = 0; j < 4; j++) acc[i][j] = 0.f;

    for (int k = 0; k < 64; k++) {
        float av[4], bv[4];
        #pragma unroll
        for (int i = 0; i < 4; i++) av[i] = sh[(tr + 16 * i) * 65 + k];
        #pragma unroll
        for (int j = 0; j < 4; j++) bv[j] = sW[k * 65 + tc + 16 * j];
        #pragma unroll
        for (int i = 0; i < 4; i++)
            #pragma unroll
            for (int j = 0; j < 4; j++) acc[i][j] = fmaf(av[i], bv[j], acc[i][j]);
    }
    __syncthreads();

    // write Wh to global and stash in smem (reuse sW) for s1/s2 dots
    #pragma unroll
    for (int i = 0; i < 4; i++) {
        const int r = tr + 16 * i;
        #pragma unroll
        for (int j = 0; j < 4; j++) {
            const int c = tc + 16 * j;
            sW[r * 65 + c] = acc[i][j];
            S.Wh[((size_t)head * NN + (n0 + r)) * HIDC + c] = acc[i][j];
        }
    }
    __syncthreads();

    if (t < 64) {
        const int r = t;
        const float* ap1 = a1 + head * HIDC;
        const float* ap2 = a2 + head * HIDC;
        float v1 = 0.f, v2 = 0.f;
        #pragma unroll
        for (int c = 0; c < 64; c++) {
            const float w = sW[r * 65 + c];
            v1 = fmaf(w, ap1[c], v1);
            v2 = fmaf(w, ap2[c], v2);
        }
        S.s1[head * NN + n0 + r] = v1;
        S.s2[head * NN + n0 + r] = v2;
    }
}

// ---------------------------------------------------------------------------
// Kernel 2: hcat @ W_out + s1o/s2o.  grid 256, block 256 (16 rows x 16 cols)
// ---------------------------------------------------------------------------
__global__ void k_gemm2(const float* __restrict__ Wo,
                        const float* __restrict__ a1,
                        const float* __restrict__ a2)
{
    __shared__ float sW[256 * 17];
    __shared__ float sh2[16 * 257];
    __shared__ float sAcc[16 * 17];

    const int row0 = blockIdx.x * 16;
    const int t    = threadIdx.x;

    for (int idx = t; idx < 4096; idx += 256)
        sW[(idx >> 4) * 17 + (idx & 15)] = Wo[idx];
    #pragma unroll
    for (int r = 0; r < 16; r++)
        sh2[r * 257 + t] = S.hcat[(size_t)(row0 + r) * 256 + t];
    __syncthreads();

    const int tc = t & 15, tr = t >> 4;
    float acc = 0.f;
    for (int k = 0; k < 256; k++)
        acc = fmaf(sh2[tr * 257 + k], sW[k * 17 + tc], acc);

    S.Wh2[(row0 + tr) * TT + tc] = acc;
    sAcc[tr * 17 + tc] = acc;
    __syncthreads();

    if (t < 16) {
        const int r = t;
        float v1 = 0.f, v2 = 0.f;
        #pragma unroll
        for (int c = 0; c < 16; c++) {
            const float w = sAcc[r * 17 + c];
            v1 = fmaf(w, a1[c], v1);
            v2 = fmaf(w, a2[c], v2);
        }
        S.s1o[row0 + r] = v1;
        S.s2o[row0 + r] = v2;
    }
}

// ---------------------------------------------------------------------------
// Kernel 3: bitonic sort of s2 (4096 elems) + exp weights.  block 1024, 1 blk/head
// ---------------------------------------------------------------------------
__global__ void k_sort(const float* __restrict__ s2,
                       float* __restrict__ s2s,
                       int* __restrict__ perm,
                       float* __restrict__ A,
                       float* __restrict__ B)
{
    __shared__ float key[NN];
    __shared__ int   sidx[NN];
    const int base = blockIdx.x * NN;
    const int t = threadIdx.x;

    #pragma unroll
    for (int m = 0; m < 4; m++) {
        const int i = t + m * 1024;
        key[i] = s2[base + i];
        sidx[i] = i;
    }
    __syncthreads();

    for (int k = 2; k <= NN; k <<= 1) {
        for (int j = k >> 1; j > 0; j >>= 1) {
            #pragma unroll
            for (int m = 0; m < 4; m++) {
                const int i = t + m * 1024;
                const int ixj = i ^ j;
                if (ixj > i) {
                    const bool up = ((i & k) == 0);
                    const float a = key[i], b = key[ixj];
                    if ((a > b) == up) {
                        key[i] = b; key[ixj] = a;
                        const int tmp = sidx[i]; sidx[i] = sidx[ixj]; sidx[ixj] = tmp;
                    }
                }
            }
            __syncthreads();
        }
    }

    #pragma unroll
    for (int m = 0; m < 4; m++) {
        const int i = t + m * 1024;
        const float v = key[i];
        s2s[base + i]  = v;
        perm[base + i] = sidx[i];
        A[base + i]    = expf(v);
        B[base + i]    = expf(0.01f * v);
    }
}

// ---------------------------------------------------------------------------
// Kernel 4: per-chunk fp64 column sums of A*Wh[perm] and B*Wh[perm]
// ---------------------------------------------------------------------------
template<int C, int CPB>
__global__ void k_chunksum(const float* __restrict__ Wh,
                           const int* __restrict__ perm,
                           const float* __restrict__ A,
                           const float* __restrict__ B,
                           double* __restrict__ csA,
                           double* __restrict__ csB)
{
    const int head = blockIdx.x;
    Wh   += (size_t)head * NN * C;
    perm += head * NN;
    A    += head * NN;
    B    += head * NN;
    csA  += head * NCHUNK * C;
    csB  += head * NCHUNK * C;

    const int c = threadIdx.x % C;
    const int q = blockIdx.y * CPB + threadIdx.x / C;
    const int p0 = q * CHSZ;
    double sa = 0.0, sb = 0.0;
    for (int e = 0; e < CHSZ; e++) {
        const int p = p0 + e;
        const float w = Wh[(size_t)perm[p] * C + c];
        sa += (double)A[p] * w;
        sb += (double)B[p] * w;
    }
    csA[q * C + c] = sa;
    csB[q * C + c] = sb;
}

// Kernel 5: scan chunk sums -> exclusive prefix (B) / exclusive suffix (A) offsets
template<int C>
__global__ void k_chunkscan(double* __restrict__ csA, double* __restrict__ csB)
{
    const int head = blockIdx.x;
    csA += head * NCHUNK * C;
    csB += head * NCHUNK * C;
    const int c = threadIdx.x;

    double run = 0.0;
    for (int q = 0; q < NCHUNK; q++) {
        const double v = csB[q * C + c];
        csB[q * C + c] = run;
        run += v;
    }
    run = 0.0;
    for (int q = NCHUNK - 1; q >= 0; q--) {
        const double v = csA[q * C + c];
        csA[q * C + c] = run;
        run += v;
    }
}

// Kernel 6: write full-resolution prefix/suffix arrays
template<int C, int CPB>
__global__ void k_pass3(const float* __restrict__ Wh,
                        const int* __restrict__ perm,
                        const float* __restrict__ A,
                        const float* __restrict__ B,
                        const double* __restrict__ csA,
                        const double* __restrict__ csB,
                        float* __restrict__ sufA,
                        float* __restrict__ preB)
{
    const int head = blockIdx.x;
    Wh   += (size_t)head * NN * C;
    perm += head * NN;
    A    += head * NN;
    B    += head * NN;
    csA  += head * NCHUNK * C;
    csB  += head * NCHUNK * C;
    sufA += (size_t)head * (NN + 1) * C;
    preB += (size_t)head * (NN + 1) * C;

    const int c = threadIdx.x % C;
    const int q = blockIdx.y * CPB + threadIdx.x / C;
    const int p0 = q * CHSZ;

    double run = csB[q * C + c];
    for (int e = 0; e < CHSZ; e++) {
        const int p = p0 + e;
        preB[(size_t)p * C + c] = (float)run;
        run += (double)B[p] * Wh[(size_t)perm[p] * C + c];
    }
    if (q == NCHUNK - 1) preB[(size_t)NN * C + c] = (float)run;

    run = csA[q * C + c];
    if (q == NCHUNK - 1) sufA[(size_t)NN * C + c] = 0.f;
    for (int e = CHSZ - 1; e >= 0; e--) {
        const int p = p0 + e;
        run += (double)A[p] * Wh[(size_t)perm[p] * C + c];
        sufA[(size_t)p * C + c] = (float)run;
    }
}

// Kernel 7: scalar prefix(B)/suffix(A) sums in fp64.  block 256, 1 blk/head
__global__ void k_scalarscan(const float* __restrict__ A,
                             const float* __restrict__ B,
                             double* __restrict__ sufAsc,
                             double* __restrict__ preBsc)
{
    __shared__ double segA[256], segB[256];
    __shared__ double totA, totB;
    const int head = blockIdx.x;
    A      += head * NN;
    B      += head * NN;
    sufAsc += head * (NN + 1);
    preBsc += head * (NN + 1);

    const int t = threadIdx.x;
    const int base = t * 16;
    double la = 0.0, lb = 0.0;
    #pragma unroll
    for (int e = 0; e < 16; e++) { la += A[base + e]; lb += B[base + e]; }
    segA[t] = la; segB[t] = lb;
    __syncthreads();

    if (t == 0) {
        double ra = 0.0, rb = 0.0;
        for (int s = 0; s < 256; s++) {
            const double ta = segA[s]; segA[s] = ra; ra += ta;
            const double tb = segB[s]; segB[s] = rb; rb += tb;
        }
        totA = ra; totB = rb;
    }
    __syncthreads();

    double runB = segB[t];
    double preA = segA[t];
    const double tA = totA;
    #pragma unroll
    for (int e = 0; e < 16; e++) {
        const int p = base + e;
        preBsc[p] = runB;      runB += B[p];
        sufAsc[p] = tA - preA; preA += A[p];
    }
    if (t == 255) { preBsc[NN] = runB; sufAsc[NN] = 0.0; }
}

// ---------------------------------------------------------------------------
// Kernel 8: per-row combine: binary search split point, assemble numer/denom,
// subtract diagonal, optional ELU.  block 256 = (256/C) rows x C channels.
// ---------------------------------------------------------------------------
template<int C, bool DO_ELU>
__global__ void k_combine(const float* __restrict__ s1,
                          const float* __restrict__ s2,
                          const float* __restrict__ s2s,
                          const float* __restrict__ Wh,
                          const float* __restrict__ sufA,
                          const float* __restrict__ preB,
                          const double* __restrict__ sufAsc,
                          const double* __restrict__ preBsc,
                          float* __restrict__ out,
                          int rowStride)
{
    const int head = blockIdx.y;
    s1     += head * NN;
    s2     += head * NN;
    s2s    += head * NN;
    Wh     += (size_t)head * NN * C;
    sufA   += (size_t)head * (NN + 1) * C;
    preB   += (size_t)head * (NN + 1) * C;
    sufAsc += head * (NN + 1);
    preBsc += head * (NN + 1);

    constexpr int IPB = 256 / C;
    const int i = blockIdx.x * IPB + threadIdx.x / C;
    const int c = threadIdx.x % C;

    const float s1v = s1[i];
    const float ea  = expf(s1v);
    const float eb  = expf(0.01f * s1v);

    // lower_bound(s2s, -s1v): first p with s2s[p] >= -s1v
    const float target = -s1v;
    int lo = 0, hi = NN;
    while (lo < hi) {
        const int mid = (lo + hi) >> 1;
        if (s2s[mid] < target) lo = mid + 1; else hi = mid;
    }
    const int k = lo;

    const float tii = s1v + s2[i];
    const float wii = expf(tii >= 0.f ? tii : 0.01f * tii);

    const double denom = (double)ea * sufAsc[k] + (double)eb * preBsc[k] - (double)wii;
    const float num = ea * sufA[(size_t)k * C + c]
                    + eb * preB[(size_t)k * C + c]
                    - wii * Wh[(size_t)i * C + c];
    float v = (float)((double)num / denom);
    if (DO_ELU) v = (v > 0.f) ? v : expm1f(v);

    out[(size_t)i * rowStride + head * C + c] = v;
}

// helper kernels need raw pointers into S; take them via device-side symbol
// references bound at launch using plain device pointers derived on host is
// disallowed-free; instead we use small wrapper kernels? Simpler: pass
// nothing — kernels above already take pointers; we obtain them via
// __device__ globals' addresses, which the compiler resolves per-kernel when
// referenced directly. To keep the generic templates, we add thin wrappers.

__global__ void k_sort1_wrap() {}  // (unused placeholder removed below)

// ---------------------------------------------------------------------------
// launch — kernel launches ONLY; scratch addresses resolved via device lambdas
// ---------------------------------------------------------------------------

// Thin launchers that bind template kernels to S's members from device code
// would complicate things; instead note that taking the address of a
// __device__ variable in HOST code is invalid, but passing sub-pointers is
// needed. Solution: a tiny setup kernel publishes pointers into a device
// pointer table that subsequent kernels read... that adds a launch. Simplest
// legal approach: kernels index into S directly via constexpr offsets.
// The template kernels above take pointers; we wrap them:

template<int C, int CPB, int L>   // L: 0 = layer1, 1 = layer2
__global__ void k_chunksum_w()
{
    const float*  Wh   = (L == 0) ? S.Wh   : S.Wh2;
    const int*    perm = (L == 0) ? S.perm : S.permo;
    const float*  A    = (L == 0) ? S.A    : S.Ao;
    const float*  B    = (L == 0) ? S.B    : S.Bo;
    double*       csA  = (L == 0) ? S.csA  : S.csA2;
    double*       csB  = (L == 0) ? S.csB  : S.csB2;

    const int head = blockIdx.x;
    Wh   += (size_t)head * NN * C;  perm += head * NN;
    A    += head * NN;              B    += head * NN;
    csA  += head * NCHUNK * C;      csB  += head * NCHUNK * C;

    const int c = threadIdx.x % C;
    const int q = blockIdx.y * CPB + threadIdx.x / C;
    const int p0 = q * CHSZ;
    double sa = 0.0, sb = 0.0;
    for (int e = 0; e < CHSZ; e++) {
        const int p = p0 + e;
        const float w = Wh[(size_t)perm[p] * C + c];
        sa += (double)A[p] * w;
        sb += (double)B[p] * w;
    }
    csA[q * C + c] = sa;
    csB[q * C + c] = sb;
}

template<int C, int L>
__global__ void k_chunkscan_w()
{
    double* csA = (L == 0) ? S.csA : S.csA2;
    double* csB = (L == 0) ? S.csB : S.csB2;
    const int head = blockIdx.x;
    csA += head * NCHUNK * C;
    csB += head * NCHUNK * C;
    const int c = threadIdx.x;

    double run = 0.0;
    for (int q = 0; q < NCHUNK; q++) {
        const double v = csB[q * C + c];
        csB[q * C + c] = run;
        run += v;
    }
    run = 0.0;
    for (int q = NCHUNK - 1; q >= 0; q--) {
        const double v = csA[q * C + c];
        csA[q * C + c] = run;
        run += v;
    }
}

template<int C, int CPB, int L>
__global__ void k_pass3_w()
{
    const float*  Wh   = (L == 0) ? S.Wh   : S.Wh2;
    const int*    perm = (L == 0) ? S.perm : S.permo;
    const float*  A    = (L == 0) ? S.A    : S.Ao;
    const float*  B    = (L == 0) ? S.B    : S.Bo;
    const double* csA  = (L == 0) ? S.csA  : S.csA2;
    const double* csB  = (L == 0) ? S.csB  : S.csB2;
    float*        sufA = (L == 0) ? S.sufA : S.sufA2;
    float*        preB = (L == 0) ? S.preB : S.preB2;

    const int head = blockIdx.x;
    Wh   += (size_t)head * NN * C;        perm += head * NN;
    A    += head * NN;                    B    += head * NN;
    csA  += head * NCHUNK * C;            csB  += head * NCHUNK * C;
    sufA += (size_t)head * (NN + 1) * C;  preB += (size_t)head * (NN + 1) * C;

    const int c = threadIdx.x % C;
    const int q = blockIdx.y * CPB + threadIdx.x / C;
    const int p0 = q * CHSZ;

    double run = csB[q * C + c];
    for (int e = 0; e < CHSZ; e++) {
        const int p = p0 + e;
        preB[(size_t)p * C + c] = (float)run;
        run += (double)B[p] * Wh[(size_t)perm[p] * C + c];
    }
    if (q == NCHUNK - 1) preB[(size_t)NN * C + c] = (float)run;

    run = csA[q * C + c];
    if (q == NCHUNK - 1) sufA[(size_t)NN * C + c] = 0.f;
    for (int e = CHSZ - 1; e >= 0; e--) {
        const int p = p0 + e;
        run += (double)A[p] * Wh[(size_t)perm[p] * C + c];
        sufA[(size_t)p * C + c] = (float)run;
    }
}

template<int L>
__global__ void k_sort_w()
{
    const float* s2  = (L == 0) ? S.s2  : S.s2o;
    float*       s2s = (L == 0) ? S.s2s : S.s2so;
    int*         perm= (L == 0) ? S.perm: S.permo;
    float*       A   = (L == 0) ? S.A   : S.Ao;
    float*       B   = (L == 0) ? S.B   : S.Bo;

    __shared__ float key[NN];
    __shared__ int   sidx[NN];
    const int base = blockIdx.x * NN;
    const int t = threadIdx.x;

    #pragma unroll
    for (int m = 0; m < 4; m++) {
        const int i = t + m * 1024;
        key[i] = s2[base + i];
        sidx[i] = i;
    }
    __syncthreads();

    for (int k = 2; k <= NN; k <<= 1) {
        for (int j = k >> 1; j > 0; j >>= 1) {
            #pragma unroll
            for (int m = 0; m < 4; m++) {
                const int i = t + m * 1024;
                const int ixj = i ^ j;
                if (ixj > i) {
                    const bool up = ((i & k) == 0);
                    const float a = key[i], b = key[ixj];
                    if ((a > b) == up) {
                        key[i] = b; key[ixj] = a;
                        const int tmp = sidx[i]; sidx[i] = sidx[ixj]; sidx[ixj] = tmp;
                    }
                }
            }
            __syncthreads();
        }
    }

    #pragma unroll
    for (int m = 0; m < 4; m++) {
        const int i = t + m * 1024;
        const float v = key[i];
        s2s[base + i]  = v;
        perm[base + i] = sidx[i];
        A[base + i]    = expf(v);
        B[base + i]    = expf(0.01f * v);
    }
}

template<int L>
__global__ void k_scalarscan_w()
{
    const float* A      = (L == 0) ? S.A      : S.Ao;
    const float* B      = (L == 0) ? S.B      : S.Bo;
    double*      sufAsc = (L == 0) ? S.sufAsc : S.sufA2sc;
    double*      preBsc = (L == 0) ? S.preBsc : S.preB2sc;

    __shared__ double segA[256], segB[256];
    __shared__ double totA, totB;
    const int head = blockIdx.x;
    A      += head * NN;
    B      += head * NN;
    sufAsc += head * (NN + 1);
    preBsc += head * (NN + 1);

    const int t = threadIdx.x;
    const int base = t * 16;
    double la = 0.0, lb = 0.0;
    #pragma unroll
    for (int e = 0; e < 16; e++) { la += A[base + e]; lb += B[base + e]; }
    segA[t] = la; segB[t] = lb;
    __syncthreads();

    if (t == 0) {
        double ra = 0.0, rb = 0.0;
        for (int s = 0; s < 256; s++) {
            const double ta = segA[s]; segA[s] = ra; ra += ta;
            const double tb = segB[s]; segB[s] = rb; rb += tb;
        }
        totA = ra; totB = rb;
    }
    __syncthreads();

    double runB = segB[t];
    double preA = segA[t];
    const double tA = totA;
    #pragma unroll
    for (int e = 0; e < 16; e++) {
        const int p = base + e;
        preBsc[p] = runB;      runB += B[p];
        sufAsc[p] = tA - preA; preA += A[p];
    }
    if (t == 255) { preBsc[NN] = runB; sufAsc[NN] = 0.0; }
}

template<int C, bool DO_ELU, int L>
__global__ void k_combine_w(float* __restrict__ extOut, int rowStride)
{
    const float*  s1     = (L == 0) ? S.s1     : S.s1o;
    const float*  s2     = (L == 0) ? S.s2     : S.s2o;
    const float*  s2s    = (L == 0) ? S.s2s    : S.s2so;
    const float*  Wh     = (L == 0) ? S.Wh     : S.Wh2;
    const float*  sufA   = (L == 0) ? S.sufA   : S.sufA2;
    const float*  preB   = (L == 0) ? S.preB   : S.preB2;
    const double* sufAsc = (L == 0) ? S.sufAsc : S.sufA2sc;
    const double* preBsc = (L == 0) ? S.preBsc : S.preB2sc;
    float* out = (L == 0) ? S.hcat : extOut;

    const int head = blockIdx.y;
    s1     += head * NN;
    s2     += head * NN;
    s2s    += head * NN;
    Wh     += (size_t)head * NN * C;
    sufA   += (size_t)head * (NN + 1) * C;
    preB   += (size_t)head * (NN + 1) * C;
    sufAsc += head * (NN + 1);
    preBsc += head * (NN + 1);

    constexpr int IPB = 256 / C;
    const int i = blockIdx.x * IPB + threadIdx.x / C;
    const int c = threadIdx.x % C;

    const float s1v = s1[i];
    const float ea  = expf(s1v);
    const float eb  = expf(0.01f * s1v);

    const float target = -s1v;
    int lo = 0, hi = NN;
    while (lo < hi) {
        const int mid = (lo + hi) >> 1;
        if (s2s[mid] < target) lo = mid + 1; else hi = mid;
    }
    const int k = lo;

    const float tii = s1v + s2[i];
    const float wii = expf(tii >= 0.f ? tii : 0.01f * tii);

    const double denom = (double)ea * sufAsc[k] + (double)eb * preBsc[k] - (double)wii;
    const float num = ea * sufA[(size_t)k * C + c]
                    + eb * preB[(size_t)k * C + c]
                    - wii * Wh[(size_t)i * C + c];
    float v = (float)((double)num / denom);
    if (DO_ELU) v = (v > 0.f) ? v : expm1f(v);

    out[(size_t)i * rowStride + head * C + c] = v;
}

extern "C" void kernel_launch(void* const* d_in, const int* in_sizes, int n_in,
                              void* d_out, int out_size)
{
    const float* x       = (const float*)d_in[0];
    const float* W_heads = (const float*)d_in[3];
    const float* a1h     = (const float*)d_in[4];
    const float* a2h     = (const float*)d_in[5];
    const float* W_out   = (const float*)d_in[6];
    const float* a1o     = (const float*)d_in[7];
    const float* a2o     = (const float*)d_in[8];
    float* out = (float*)d_out;

    // ---- layer 1 (4 heads) ----
    k_gemm1<<<dim3(NN / 64, NH), 256>>>(x, W_heads, a1h, a2h);
    k_sort_w<0><<<NH, 1024>>>();
    k_chunksum_w<HIDC, 4, 0><<<dim3(NH, NCHUNK / 4), 256>>>();
    k_chunkscan_w<HIDC, 0><<<NH, HIDC>>>();
    k_pass3_w<HIDC, 4, 0><<<dim3(NH, NCHUNK / 4), 256>>>();
    k_scalarscan_w<0><<<NH, 256>>>();
    k_combine_w<HIDC, true, 0><<<dim3(NN / 4, NH), 256>>>(nullptr, NH * HIDC);

    // ---- layer 2 (output) ----
    k_gemm2<<<NN / 16, 256>>>(W_out, a1o, a2o);
    k_sort_w<1><<<1, 1024>>>();
    k_chunksum_w<TT, 16, 1><<<dim3(1, NCHUNK / 16), 256>>>();
    k_chunkscan_w<TT, 1><<<1, TT>>>();
    k_pass3_w<TT, 16, 1><<<dim3(1, NCHUNK / 16), 256>>>();
    k_scalarscan_w<1><<<1, 256>>>();
    k_combine_w<TT, false, 1><<<dim3(NN / 16, 1), 256>>>(out, TT);
}

// round 4
// speedup vs baseline: 1.1062x; 1.1062x over previous
#include <cuda_runtime.h>
#include <math.h>
#include <stddef.h>

// Problem constants
#define NN    4096      // nodes
#define TT    16        // timesteps / out features
#define FF    4         // node features
#define HIDC  64        // hidden per head
#define NH    4         // heads
#define NCHUNK 64
#define CHSZ   64       // NN / NCHUNK

// ---------------------------------------------------------------------------
// Scratch (static device global)
// ---------------------------------------------------------------------------
struct Scratch {
    // layer 1
    float  Wh[NH * NN * HIDC];
    float  s1[NH * NN];
    float  s2[NH * NN];
    float  s2s[NH * NN];
    int    perm[NH * NN];
    float  A[NH * NN];                 // exp(s2_sorted)
    float  B[NH * NN];                 // exp(0.01*s2_sorted)
    float  csA[NH * NCHUNK * HIDC];    // per-chunk sums (A-weighted)
    float  csB[NH * NCHUNK * HIDC];    // per-chunk sums (B-weighted)
    float  sufA[NH * (NN + 1) * HIDC];
    float  preB[NH * (NN + 1) * HIDC];
    double sufAsc[NH * (NN + 1)];
    double preBsc[NH * (NN + 1)];
    float  hcat[NN * NH * HIDC];
    // layer 2
    float  Wh2[NN * TT];
    float  s1o[NN], s2o[NN], s2so[NN];
    int    permo[NN];
    float  Ao[NN], Bo[NN];
    float  csA2[NCHUNK * TT], csB2[NCHUNK * TT];
    float  sufA2[(NN + 1) * TT], preB2[(NN + 1) * TT];
    double sufA2sc[NN + 1], preB2sc[NN + 1];
};
__device__ Scratch S;

// ---------------------------------------------------------------------------
// Kernel 1: fused transpose(x) -> h, Wh = h @ W[head], s1/s2 dots
// grid (NN/64, NH), block 256
// ---------------------------------------------------------------------------
__global__ void k_gemm1(const float* __restrict__ x,
                        const float* __restrict__ W,
                        const float* __restrict__ a1,
                        const float* __restrict__ a2)
{
    __shared__ float sW[64 * 65];
    __shared__ float sh[64 * 65];

    const int head = blockIdx.y;
    const int n0   = blockIdx.x * 64;
    const int t    = threadIdx.x;

    const float* Wp = W + head * 64 * 64;
    for (int idx = t; idx < 4096; idx += 256)
        sW[(idx >> 6) * 65 + (idx & 63)] = Wp[idx];

    {
        const int dn = t >> 2, f = t & 3;
        #pragma unroll
        for (int tt = 0; tt < TT; tt++)
            sh[dn * 65 + tt * 4 + f] = x[(size_t)tt * NN * FF + (size_t)(n0 + dn) * FF + f];
    }
    __syncthreads();

    const int tc = t & 15, tr = t >> 4;
    float acc[4][4];
    #pragma unroll
    for (int i = 0; i < 4; i++)
        #pragma unroll
        for (int j = 0; j < 4; j++) acc[i][j] = 0.f;

    for (int k = 0; k < 64; k++) {
        float av[4], bv[4];
        #pragma unroll
        for (int i = 0; i < 4; i++) av[i] = sh[(tr + 16 * i) * 65 + k];
        #pragma unroll
        for (int j = 0; j < 4; j++) bv[j] = sW[k * 65 + tc + 16 * j];
        #pragma unroll
        for (int i = 0; i < 4; i++)
            #pragma unroll
            for (int j = 0; j < 4; j++) acc[i][j] = fmaf(av[i], bv[j], acc[i][j]);
    }
    __syncthreads();

    #pragma unroll
    for (int i = 0; i < 4; i++) {
        const int r = tr + 16 * i;
        #pragma unroll
        for (int j = 0; j < 4; j++) {
            const int c = tc + 16 * j;
            sW[r * 65 + c] = acc[i][j];
            S.Wh[((size_t)head * NN + (n0 + r)) * HIDC + c] = acc[i][j];
        }
    }
    __syncthreads();

    if (t < 64) {
        const int r = t;
        const float* ap1 = a1 + head * HIDC;
        const float* ap2 = a2 + head * HIDC;
        float v1 = 0.f, v2 = 0.f;
        #pragma unroll
        for (int c = 0; c < 64; c++) {
            const float w = sW[r * 65 + c];
            v1 = fmaf(w, ap1[c], v1);
            v2 = fmaf(w, ap2[c], v2);
        }
        S.s1[head * NN + n0 + r] = v1;
        S.s2[head * NN + n0 + r] = v2;
    }
}

// ---------------------------------------------------------------------------
// Kernel 2: hcat @ W_out + s1o/s2o.  grid 256, block 256
// ---------------------------------------------------------------------------
__global__ void k_gemm2(const float* __restrict__ Wo,
                        const float* __restrict__ a1,
                        const float* __restrict__ a2)
{
    __shared__ float sW[256 * 17];
    __shared__ float sh2[16 * 257];
    __shared__ float sAcc[16 * 17];

    const int row0 = blockIdx.x * 16;
    const int t    = threadIdx.x;

    for (int idx = t; idx < 4096; idx += 256)
        sW[(idx >> 4) * 17 + (idx & 15)] = Wo[idx];
    #pragma unroll
    for (int r = 0; r < 16; r++)
        sh2[r * 257 + t] = S.hcat[(size_t)(row0 + r) * 256 + t];
    __syncthreads();

    const int tc = t & 15, tr = t >> 4;
    float acc = 0.f;
    for (int k = 0; k < 256; k++)
        acc = fmaf(sh2[tr * 257 + k], sW[k * 17 + tc], acc);

    S.Wh2[(row0 + tr) * TT + tc] = acc;
    sAcc[tr * 17 + tc] = acc;
    __syncthreads();

    if (t < 16) {
        const int r = t;
        float v1 = 0.f, v2 = 0.f;
        #pragma unroll
        for (int c = 0; c < 16; c++) {
            const float w = sAcc[r * 17 + c];
            v1 = fmaf(w, a1[c], v1);
            v2 = fmaf(w, a2[c], v2);
        }
        S.s1o[row0 + r] = v1;
        S.s2o[row0 + r] = v2;
    }
}

// ---------------------------------------------------------------------------
// Kernel 3: bitonic sort (register/shuffle-accelerated) + exp weights +
// fused fp64 scalar prefix/suffix scans.  1 block of 1024 per head.
// ---------------------------------------------------------------------------
template<int L>
__global__ void k_sortscan()
{
    const float* s2  = (L == 0) ? S.s2  : S.s2o;
    float*       s2s = (L == 0) ? S.s2s : S.s2so;
    int*         perm= (L == 0) ? S.perm: S.permo;
    float*       A   = (L == 0) ? S.A   : S.Ao;
    float*       B   = (L == 0) ? S.B   : S.Bo;
    double*      sufAsc = (L == 0) ? S.sufAsc : S.sufA2sc;
    double*      preBsc = (L == 0) ? S.preBsc : S.preB2sc;

    __shared__ float key[NN];
    __shared__ int   sidx[NN];          // reused as double seg[2048] later

    const int base = blockIdx.x * NN;
    const int t    = threadIdx.x;
    const int lane = t & 31;
    sufAsc += blockIdx.x * (NN + 1);
    preBsc += blockIdx.x * (NN + 1);

    float k0[4]; int x0[4];
    #pragma unroll
    for (int m = 0; m < 4; m++) {
        const int i = t + m * 1024;
        k0[m] = s2[base + i];
        x0[m] = i;
    }

    // stages k=2..32 entirely in registers (partner always in-warp)
    #pragma unroll
    for (int k = 2; k <= 32; k <<= 1) {
        #pragma unroll
        for (int j = k >> 1; j >= 1; j >>= 1) {
            #pragma unroll
            for (int m = 0; m < 4; m++) {
                const int i = t + m * 1024;
                const bool up = ((i & k) == 0);
                const float ok = __shfl_xor_sync(0xffffffffu, k0[m], j);
                const int   oi = __shfl_xor_sync(0xffffffffu, x0[m], j);
                const bool lower = ((lane & j) == 0);
                const bool wantMin = (lower == up);
                const bool take = wantMin ? (ok < k0[m]) : (ok > k0[m]);
                if (take) { k0[m] = ok; x0[m] = oi; }
            }
        }
    }
    #pragma unroll
    for (int m = 0; m < 4; m++) {
        const int i = t + m * 1024;
        key[i] = k0[m]; sidx[i] = x0[m];
    }
    __syncthreads();

    // stages k=64..4096: smem passes down to j=32, then in-warp shuffle tail
    for (int k = 64; k <= NN; k <<= 1) {
        for (int j = k >> 1; j >= 32; j >>= 1) {
            #pragma unroll
            for (int m = 0; m < 4; m++) {
                const int i = t + m * 1024;
                const int ixj = i ^ j;
                if (ixj > i) {
                    const bool up = ((i & k) == 0);
                    const float a = key[i], b = key[ixj];
                    if ((a > b) == up) {
                        key[i] = b; key[ixj] = a;
                        const int tmp = sidx[i]; sidx[i] = sidx[ixj]; sidx[ixj] = tmp;
                    }
                }
            }
            __syncthreads();
        }
        #pragma unroll
        for (int m = 0; m < 4; m++) {
            const int i = t + m * 1024;
            k0[m] = key[i]; x0[m] = sidx[i];
        }
        #pragma unroll
        for (int j = 16; j >= 1; j >>= 1) {
            #pragma unroll
            for (int m = 0; m < 4; m++) {
                const int i = t + m * 1024;
                const bool up = ((i & k) == 0);
                const float ok = __shfl_xor_sync(0xffffffffu, k0[m], j);
                const int   oi = __shfl_xor_sync(0xffffffffu, x0[m], j);
                const bool lower = ((lane & j) == 0);
                const bool wantMin = (lower == up);
                const bool take = wantMin ? (ok < k0[m]) : (ok > k0[m]);
                if (take) { k0[m] = ok; x0[m] = oi; }
            }
        }
        #pragma unroll
        for (int m = 0; m < 4; m++) {
            const int i = t + m * 1024;
            key[i] = k0[m]; sidx[i] = x0[m];
        }
        __syncthreads();
    }

    // write sorted keys / perm / exp weights from registers
    #pragma unroll
    for (int m = 0; m < 4; m++) {
        const int i = t + m * 1024;
        const float v = k0[m];
        s2s[base + i]  = v;
        perm[base + i] = x0[m];
        A[base + i]    = expf(v);
        B[base + i]    = expf(0.01f * v);
    }
    __syncthreads();

    // fused scalar scans (fp64): thread t owns positions 4t..4t+3
    double* seg = (double*)sidx;     // 2048 doubles: segA[0..1023], segB[1024..2047]
    float av[4], bv[4];
    double la = 0.0, lb = 0.0;
    #pragma unroll
    for (int e = 0; e < 4; e++) {
        const float v = key[4 * t + e];
        av[e] = expf(v); bv[e] = expf(0.01f * v);
        la += (double)av[e]; lb += (double)bv[e];
    }
    seg[t] = la; seg[1024 + t] = lb;
    __syncthreads();

    for (int d = 1; d < 1024; d <<= 1) {
        double va = 0.0, vb = 0.0;
        if (t >= d) { va = seg[t - d]; vb = seg[1024 + t - d]; }
        __syncthreads();
        seg[t] += va; seg[1024 + t] += vb;
        __syncthreads();
    }

    const double exA = seg[t] - la;
    const double exB = seg[1024 + t] - lb;
    const double totA = seg[1023];
    const double totB = seg[2047];

    double runB = exB, runA = exA;
    #pragma unroll
    for (int e = 0; e < 4; e++) {
        const int p = 4 * t + e;
        preBsc[p] = runB;        runB += (double)bv[e];
        sufAsc[p] = totA - runA; runA += (double)av[e];
    }
    if (t == 1023) { preBsc[NN] = totB; sufAsc[NN] = 0.0; }
}

// ---------------------------------------------------------------------------
// Kernel 4: per-chunk fp32 column sums of A*Wh[perm] and B*Wh[perm]
// ---------------------------------------------------------------------------
template<int C, int CPB, int L>
__global__ void k_chunksum()
{
    const float*  Wh   = (L == 0) ? S.Wh   : S.Wh2;
    const int*    perm = (L == 0) ? S.perm : S.permo;
    const float*  A    = (L == 0) ? S.A    : S.Ao;
    const float*  B    = (L == 0) ? S.B    : S.Bo;
    float*        csA  = (L == 0) ? S.csA  : S.csA2;
    float*        csB  = (L == 0) ? S.csB  : S.csB2;

    const int head = blockIdx.x;
    Wh   += (size_t)head * NN * C;  perm += head * NN;
    A    += head * NN;              B    += head * NN;
    csA  += head * NCHUNK * C;      csB  += head * NCHUNK * C;

    const int c = threadIdx.x % C;
    const int q = blockIdx.y * CPB + threadIdx.x / C;
    const int p0 = q * CHSZ;
    float sa = 0.f, sb = 0.f;
    #pragma unroll 4
    for (int e = 0; e < CHSZ; e++) {
        const int p = p0 + e;
        const float w = Wh[(size_t)perm[p] * C + c];
        sa = fmaf(A[p], w, sa);
        sb = fmaf(B[p], w, sb);
    }
    csA[q * C + c] = sa;
    csB[q * C + c] = sb;
}

// ---------------------------------------------------------------------------
// Kernel 5: full-resolution prefix/suffix arrays; each thread computes its own
// cross-chunk offsets (64 independent coalesced loads, fp32 chain).
// ---------------------------------------------------------------------------
template<int C, int CPB, int L>
__global__ void k_pass3()
{
    const float*  Wh   = (L == 0) ? S.Wh   : S.Wh2;
    const int*    perm = (L == 0) ? S.perm : S.permo;
    const float*  A    = (L == 0) ? S.A    : S.Ao;
    const float*  B    = (L == 0) ? S.B    : S.Bo;
    const float*  csA  = (L == 0) ? S.csA  : S.csA2;
    const float*  csB  = (L == 0) ? S.csB  : S.csB2;
    float*        sufA = (L == 0) ? S.sufA : S.sufA2;
    float*        preB = (L == 0) ? S.preB : S.preB2;

    const int head = blockIdx.x;
    Wh   += (size_t)head * NN * C;        perm += head * NN;
    A    += head * NN;                    B    += head * NN;
    csA  += head * NCHUNK * C;            csB  += head * NCHUNK * C;
    sufA += (size_t)head * (NN + 1) * C;  preB += (size_t)head * (NN + 1) * C;

    const int c = threadIdx.x % C;
    const int q = blockIdx.y * CPB + threadIdx.x / C;
    const int p0 = q * CHSZ;

    // cross-chunk offsets (exclusive prefix for B, exclusive suffix for A)
    float offB = 0.f, offA = 0.f;
    #pragma unroll 4
    for (int qq = 0; qq < NCHUNK; qq++) {
        const float vB = csB[qq * C + c];
        const float vA = csA[qq * C + c];
        if (qq < q) offB += vB;
        if (qq > q) offA += vA;
    }

    float run = offB;
    #pragma unroll 4
    for (int e = 0; e < CHSZ; e++) {
        const int p = p0 + e;
        preB[(size_t)p * C + c] = run;
        run = fmaf(B[p], Wh[(size_t)perm[p] * C + c], run);
    }
    if (q == NCHUNK - 1) preB[(size_t)NN * C + c] = run;

    run = offA;
    if (q == NCHUNK - 1) sufA[(size_t)NN * C + c] = 0.f;
    #pragma unroll 4
    for (int e = CHSZ - 1; e >= 0; e--) {
        const int p = p0 + e;
        run = fmaf(A[p], Wh[(size_t)perm[p] * C + c], run);
        sufA[(size_t)p * C + c] = run;
    }
}

// ---------------------------------------------------------------------------
// Kernel 6: per-row combine
// ---------------------------------------------------------------------------
template<int C, bool DO_ELU, int L>
__global__ void k_combine(float* __restrict__ extOut, int rowStride)
{
    const float*  s1     = (L == 0) ? S.s1     : S.s1o;
    const float*  s2     = (L == 0) ? S.s2     : S.s2o;
    const float*  s2s    = (L == 0) ? S.s2s    : S.s2so;
    const float*  Wh     = (L == 0) ? S.Wh     : S.Wh2;
    const float*  sufA   = (L == 0) ? S.sufA   : S.sufA2;
    const float*  preB   = (L == 0) ? S.preB   : S.preB2;
    const double* sufAsc = (L == 0) ? S.sufAsc : S.sufA2sc;
    const double* preBsc = (L == 0) ? S.preBsc : S.preB2sc;
    float* out = (L == 0) ? S.hcat : extOut;

    const int head = blockIdx.y;
    s1     += head * NN;
    s2     += head * NN;
    s2s    += head * NN;
    Wh     += (size_t)head * NN * C;
    sufA   += (size_t)head * (NN + 1) * C;
    preB   += (size_t)head * (NN + 1) * C;
    sufAsc += head * (NN + 1);
    preBsc += head * (NN + 1);

    constexpr int IPB = 256 / C;
    const int i = blockIdx.x * IPB + threadIdx.x / C;
    const int c = threadIdx.x % C;

    const float s1v = s1[i];
    const float ea  = expf(s1v);
    const float eb  = expf(0.01f * s1v);

    const float target = -s1v;
    int lo = 0, hi = NN;
    while (lo < hi) {
        const int mid = (lo + hi) >> 1;
        if (s2s[mid] < target) lo = mid + 1; else hi = mid;
    }
    const int k = lo;

    const float tii = s1v + s2[i];
    const float wii = expf(tii >= 0.f ? tii : 0.01f * tii);

    const double denom = (double)ea * sufAsc[k] + (double)eb * preBsc[k] - (double)wii;
    const float num = ea * sufA[(size_t)k * C + c]
                    + eb * preB[(size_t)k * C + c]
                    - wii * Wh[(size_t)i * C + c];
    float v = (float)((double)num / denom);
    if (DO_ELU) v = (v > 0.f) ? v : expm1f(v);

    out[(size_t)i * rowStride + head * C + c] = v;
}

// ---------------------------------------------------------------------------
// launch — kernel launches only (10 launches)
// ---------------------------------------------------------------------------
extern "C" void kernel_launch(void* const* d_in, const int* in_sizes, int n_in,
                              void* d_out, int out_size)
{
    const float* x       = (const float*)d_in[0];
    const float* W_heads = (const float*)d_in[3];
    const float* a1h     = (const float*)d_in[4];
    const float* a2h     = (const float*)d_in[5];
    const float* W_out   = (const float*)d_in[6];
    const float* a1o     = (const float*)d_in[7];
    const float* a2o     = (const float*)d_in[8];
    float* out = (float*)d_out;

    // ---- layer 1 (4 heads) ----
    k_gemm1<<<dim3(NN / 64, NH), 256>>>(x, W_heads, a1h, a2h);
    k_sortscan<0><<<NH, 1024>>>();
    k_chunksum<HIDC, 4, 0><<<dim3(NH, NCHUNK / 4), 256>>>();
    k_pass3<HIDC, 4, 0><<<dim3(NH, NCHUNK / 4), 256>>>();
    k_combine<HIDC, true, 0><<<dim3(NN / 4, NH), 256>>>(nullptr, NH * HIDC);

    // ---- layer 2 (output) ----
    k_gemm2<<<NN / 16, 256>>>(W_out, a1o, a2o);
    k_sortscan<1><<<1, 1024>>>();
    k_chunksum<TT, 16, 1><<<dim3(1, NCHUNK / 16), 256>>>();
    k_pass3<TT, 16, 1><<<dim3(1, NCHUNK / 16), 256>>>();
    k_combine<TT, false, 1><<<dim3(NN / 16, 1), 256>>>(out, TT);
}

// round 6
// speedup vs baseline: 1.2436x; 1.1242x over previous
#include <cuda_runtime.h>
#include <math.h>
#include <stddef.h>

// Problem constants
#define NN    4096      // nodes
#define TT    16        // timesteps / out features
#define FF    4         // node features
#define HIDC  64        // hidden per head
#define NH    4         // heads
#define NCHUNK 128
#define CHSZ   32       // NN / NCHUNK

// ---------------------------------------------------------------------------
// Scratch (static device global)
// ---------------------------------------------------------------------------
struct Scratch {
    // layer 1
    float  Wh[NH * NN * HIDC];
    float  s1[NH * NN];
    float  s2[NH * NN];
    float  s2s[NH * NN];
    int    perm[NH * NN];
    float  A[NH * NN];                 // exp(s2_sorted)
    float  B[NH * NN];                 // exp(0.01*s2_sorted)
    float  csA[NH * NCHUNK * HIDC];    // per-chunk sums (A-weighted)
    float  csB[NH * NCHUNK * HIDC];    // per-chunk sums (B-weighted)
    float  sufA[NH * (NN + 1) * HIDC];
    float  preB[NH * (NN + 1) * HIDC];
    double sufAsc[NH * (NN + 1)];
    double preBsc[NH * (NN + 1)];
    float  hcat[NN * NH * HIDC];
    // layer 2
    float  Wh2[NN * TT];
    float  s1o[NN], s2o[NN], s2so[NN];
    int    permo[NN];
    float  Ao[NN], Bo[NN];
    float  csA2[NCHUNK * TT], csB2[NCHUNK * TT];
    float  sufA2[(NN + 1) * TT], preB2[(NN + 1) * TT];
    double sufA2sc[NN + 1], preB2sc[NN + 1];
};
__device__ Scratch S;

// ---------------------------------------------------------------------------
// Kernel 1: fused transpose(x) -> h, Wh = h @ W[head], s1/s2 dots
// grid (NN/64, NH), block 256
// ---------------------------------------------------------------------------
__global__ void k_gemm1(const float* __restrict__ x,
                        const float* __restrict__ W,
                        const float* __restrict__ a1,
                        const float* __restrict__ a2)
{
    __shared__ float sW[64 * 65];
    __shared__ float sh[64 * 65];

    const int head = blockIdx.y;
    const int n0   = blockIdx.x * 64;
    const int t    = threadIdx.x;

    const float* Wp = W + head * 64 * 64;
    for (int idx = t; idx < 4096; idx += 256)
        sW[(idx >> 6) * 65 + (idx & 63)] = Wp[idx];

    {
        const int dn = t >> 2, f = t & 3;
        #pragma unroll
        for (int tt = 0; tt < TT; tt++)
            sh[dn * 65 + tt * 4 + f] = x[(size_t)tt * NN * FF + (size_t)(n0 + dn) * FF + f];
    }
    __syncthreads();

    const int tc = t & 15, tr = t >> 4;
    float acc[4][4];
    #pragma unroll
    for (int i = 0; i < 4; i++)
        #pragma unroll
        for (int j = 0; j < 4; j++) acc[i][j] = 0.f;

    for (int k = 0; k < 64; k++) {
        float av[4], bv[4];
        #pragma unroll
        for (int i = 0; i < 4; i++) av[i] = sh[(tr + 16 * i) * 65 + k];
        #pragma unroll
        for (int j = 0; j < 4; j++) bv[j] = sW[k * 65 + tc + 16 * j];
        #pragma unroll
        for (int i = 0; i < 4; i++)
            #pragma unroll
            for (int j = 0; j < 4; j++) acc[i][j] = fmaf(av[i], bv[j], acc[i][j]);
    }
    __syncthreads();

    float* __restrict__ WhG = S.Wh;
    #pragma unroll
    for (int i = 0; i < 4; i++) {
        const int r = tr + 16 * i;
        #pragma unroll
        for (int j = 0; j < 4; j++) {
            const int c = tc + 16 * j;
            sW[r * 65 + c] = acc[i][j];
            WhG[((size_t)head * NN + (n0 + r)) * HIDC + c] = acc[i][j];
        }
    }
    __syncthreads();

    if (t < 64) {
        const int r = t;
        const float* ap1 = a1 + head * HIDC;
        const float* ap2 = a2 + head * HIDC;
        float v1 = 0.f, v2 = 0.f;
        #pragma unroll
        for (int c = 0; c < 64; c++) {
            const float w = sW[r * 65 + c];
            v1 = fmaf(w, ap1[c], v1);
            v2 = fmaf(w, ap2[c], v2);
        }
        S.s1[head * NN + n0 + r] = v1;
        S.s2[head * NN + n0 + r] = v2;
    }
}

// ---------------------------------------------------------------------------
// Kernel 2: hcat @ W_out + s1o/s2o.  grid 256, block 256
// ---------------------------------------------------------------------------
__global__ void k_gemm2(const float* __restrict__ Wo,
                        const float* __restrict__ a1,
                        const float* __restrict__ a2)
{
    __shared__ float sW[256 * 17];
    __shared__ float sh2[16 * 257];
    __shared__ float sAcc[16 * 17];

    const float* __restrict__ hcat = S.hcat;
    const int row0 = blockIdx.x * 16;
    const int t    = threadIdx.x;

    for (int idx = t; idx < 4096; idx += 256)
        sW[(idx >> 4) * 17 + (idx & 15)] = Wo[idx];
    #pragma unroll
    for (int r = 0; r < 16; r++)
        sh2[r * 257 + t] = hcat[(size_t)(row0 + r) * 256 + t];
    __syncthreads();

    const int tc = t & 15, tr = t >> 4;
    float acc = 0.f;
    #pragma unroll 8
    for (int k = 0; k < 256; k++)
        acc = fmaf(sh2[tr * 257 + k], sW[k * 17 + tc], acc);

    S.Wh2[(row0 + tr) * TT + tc] = acc;
    sAcc[tr * 17 + tc] = acc;
    __syncthreads();

    if (t < 16) {
        const int r = t;
        float v1 = 0.f, v2 = 0.f;
        #pragma unroll
        for (int c = 0; c < 16; c++) {
            const float w = sAcc[r * 17 + c];
            v1 = fmaf(w, a1[c], v1);
            v2 = fmaf(w, a2[c], v2);
        }
        S.s1o[row0 + r] = v1;
        S.s2o[row0 + r] = v2;
    }
}

// ---------------------------------------------------------------------------
// Kernel 3: bitonic sort (register/shuffle) + exp weights + fused fp64 scans
// 1 block of 1024 per head.
// ---------------------------------------------------------------------------
template<int L>
__global__ void k_sortscan()
{
    const float* __restrict__ s2  = (L == 0) ? S.s2  : S.s2o;
    float*       __restrict__ s2s = (L == 0) ? S.s2s : S.s2so;
    int*         __restrict__ perm= (L == 0) ? S.perm: S.permo;
    float*       __restrict__ A   = (L == 0) ? S.A   : S.Ao;
    float*       __restrict__ B   = (L == 0) ? S.B   : S.Bo;
    double*      __restrict__ sufAsc = ((L == 0) ? S.sufAsc : S.sufA2sc) + blockIdx.x * (NN + 1);
    double*      __restrict__ preBsc = ((L == 0) ? S.preBsc : S.preB2sc) + blockIdx.x * (NN + 1);

    __shared__ float key[NN];
    __shared__ int   sidx[NN];          // reused as double seg[2048] later

    const int base = blockIdx.x * NN;
    const int t    = threadIdx.x;
    const int lane = t & 31;

    float k0[4]; int x0[4];
    #pragma unroll
    for (int m = 0; m < 4; m++) {
        const int i = t + m * 1024;
        k0[m] = s2[base + i];
        x0[m] = i;
    }

    // stages k=2..32 entirely in registers (partner always in-warp)
    #pragma unroll
    for (int k = 2; k <= 32; k <<= 1) {
        #pragma unroll
        for (int j = k >> 1; j >= 1; j >>= 1) {
            #pragma unroll
            for (int m = 0; m < 4; m++) {
                const int i = t + m * 1024;
                const bool up = ((i & k) == 0);
                const float ok = __shfl_xor_sync(0xffffffffu, k0[m], j);
                const int   oi = __shfl_xor_sync(0xffffffffu, x0[m], j);
                const bool lower = ((lane & j) == 0);
                const bool wantMin = (lower == up);
                const bool take = wantMin ? (ok < k0[m]) : (ok > k0[m]);
                if (take) { k0[m] = ok; x0[m] = oi; }
            }
        }
    }
    #pragma unroll
    for (int m = 0; m < 4; m++) {
        const int i = t + m * 1024;
        key[i] = k0[m]; sidx[i] = x0[m];
    }
    __syncthreads();

    // stages k=64..4096: smem passes down to j=32, then in-warp shuffle tail
    for (int k = 64; k <= NN; k <<= 1) {
        for (int j = k >> 1; j >= 32; j >>= 1) {
            #pragma unroll
            for (int m = 0; m < 4; m++) {
                const int i = t + m * 1024;
                const int ixj = i ^ j;
                if (ixj > i) {
                    const bool up = ((i & k) == 0);
                    const float a = key[i], b = key[ixj];
                    if ((a > b) == up) {
                        key[i] = b; key[ixj] = a;
                        const int tmp = sidx[i]; sidx[i] = sidx[ixj]; sidx[ixj] = tmp;
                    }
                }
            }
            __syncthreads();
        }
        #pragma unroll
        for (int m = 0; m < 4; m++) {
            const int i = t + m * 1024;
            k0[m] = key[i]; x0[m] = sidx[i];
        }
        #pragma unroll
        for (int j = 16; j >= 1; j >>= 1) {
            #pragma unroll
            for (int m = 0; m < 4; m++) {
                const int i = t + m * 1024;
                const bool up = ((i & k) == 0);
                const float ok = __shfl_xor_sync(0xffffffffu, k0[m], j);
                const int   oi = __shfl_xor_sync(0xffffffffu, x0[m], j);
                const bool lower = ((lane & j) == 0);
                const bool wantMin = (lower == up);
                const bool take = wantMin ? (ok < k0[m]) : (ok > k0[m]);
                if (take) { k0[m] = ok; x0[m] = oi; }
            }
        }
        #pragma unroll
        for (int m = 0; m < 4; m++) {
            const int i = t + m * 1024;
            key[i] = k0[m]; sidx[i] = x0[m];
        }
        __syncthreads();
    }

    // write sorted keys / perm / exp weights from registers
    #pragma unroll
    for (int m = 0; m < 4; m++) {
        const int i = t + m * 1024;
        const float v = k0[m];
        s2s[base + i]  = v;
        perm[base + i] = x0[m];
        A[base + i]    = expf(v);
        B[base + i]    = expf(0.01f * v);
    }
    __syncthreads();

    // fused scalar scans (fp64): thread t owns positions 4t..4t+3
    double* seg = (double*)sidx;     // 2048 doubles
    float av[4], bv[4];
    double la = 0.0, lb = 0.0;
    #pragma unroll
    for (int e = 0; e < 4; e++) {
        const float v = key[4 * t + e];
        av[e] = expf(v); bv[e] = expf(0.01f * v);
        la += (double)av[e]; lb += (double)bv[e];
    }
    seg[t] = la; seg[1024 + t] = lb;
    __syncthreads();

    for (int d = 1; d < 1024; d <<= 1) {
        double va = 0.0, vb = 0.0;
        if (t >= d) { va = seg[t - d]; vb = seg[1024 + t - d]; }
        __syncthreads();
        seg[t] += va; seg[1024 + t] += vb;
        __syncthreads();
    }

    const double exA = seg[t] - la;
    const double exB = seg[1024 + t] - lb;
    const double totA = seg[1023];
    const double totB = seg[2047];

    double runB = exB, runA = exA;
    #pragma unroll
    for (int e = 0; e < 4; e++) {
        const int p = 4 * t + e;
        preBsc[p] = runB;        runB += (double)bv[e];
        sufAsc[p] = totA - runA; runA += (double)av[e];
    }
    if (t == 1023) { preBsc[NN] = totB; sufAsc[NN] = 0.0; }
}

// ---------------------------------------------------------------------------
// Kernel 4: per-chunk fp32 column sums of A*Wh[perm] and B*Wh[perm]
// ---------------------------------------------------------------------------
template<int C, int CPB, int L>
__global__ void k_chunksum()
{
    const int head = blockIdx.x;
    const float* __restrict__ Wh   = ((L == 0) ? S.Wh   : S.Wh2) + (size_t)head * NN * C;
    const int*   __restrict__ perm = ((L == 0) ? S.perm : S.permo) + head * NN;
    const float* __restrict__ A    = ((L == 0) ? S.A    : S.Ao)   + head * NN;
    const float* __restrict__ B    = ((L == 0) ? S.B    : S.Bo)   + head * NN;
    float*       __restrict__ csA  = ((L == 0) ? S.csA  : S.csA2) + head * NCHUNK * C;
    float*       __restrict__ csB  = ((L == 0) ? S.csB  : S.csB2) + head * NCHUNK * C;

    const int c = threadIdx.x % C;
    const int q = blockIdx.y * CPB + threadIdx.x / C;
    const int p0 = q * CHSZ;
    float sa = 0.f, sb = 0.f;
    #pragma unroll 8
    for (int e = 0; e < CHSZ; e++) {
        const int p = p0 + e;
        const float w = Wh[(size_t)perm[p] * C + c];
        sa = fmaf(A[p], w, sa);
        sb = fmaf(B[p], w, sb);
    }
    csA[q * C + c] = sa;
    csB[q * C + c] = sb;
}

// ---------------------------------------------------------------------------
// Kernel 5: full-resolution prefix/suffix arrays.
// blockIdx.z = 0 -> preB (prefix of B-weighted), 1 -> sufA (suffix of A-weighted)
// ---------------------------------------------------------------------------
template<int C, int CPB, int L>
__global__ void k_pass3()
{
    const int head = blockIdx.x;
    const float* __restrict__ Wh   = ((L == 0) ? S.Wh   : S.Wh2) + (size_t)head * NN * C;
    const int*   __restrict__ perm = ((L == 0) ? S.perm : S.permo) + head * NN;
    const float* __restrict__ A    = ((L == 0) ? S.A    : S.Ao)   + head * NN;
    const float* __restrict__ B    = ((L == 0) ? S.B    : S.Bo)   + head * NN;
    const float* __restrict__ csA  = ((L == 0) ? S.csA  : S.csA2) + head * NCHUNK * C;
    const float* __restrict__ csB  = ((L == 0) ? S.csB  : S.csB2) + head * NCHUNK * C;
    float*       __restrict__ sufA = ((L == 0) ? S.sufA : S.sufA2) + (size_t)head * (NN + 1) * C;
    float*       __restrict__ preB = ((L == 0) ? S.preB : S.preB2) + (size_t)head * (NN + 1) * C;

    const int c = threadIdx.x % C;
    const int q = blockIdx.y * CPB + threadIdx.x / C;
    const int p0 = q * CHSZ;

    if (blockIdx.z == 0) {
        // exclusive prefix offset over chunks < q
        float off = 0.f;
        #pragma unroll 8
        for (int qq = 0; qq < NCHUNK; qq++) {
            const float v = csB[qq * C + c];
            if (qq < q) off += v;
        }
        float run = off;
        #pragma unroll 8
        for (int e = 0; e < CHSZ; e++) {
            const int p = p0 + e;
            preB[(size_t)p * C + c] = run;
            run = fmaf(B[p], Wh[(size_t)perm[p] * C + c], run);
        }
        if (q == NCHUNK - 1) preB[(size_t)NN * C + c] = run;
    } else {
        // exclusive suffix offset over chunks > q
        float off = 0.f;
        #pragma unroll 8
        for (int qq = 0; qq < NCHUNK; qq++) {
            const float v = csA[qq * C + c];
            if (qq > q) off += v;
        }
        float run = off;
        if (q == NCHUNK - 1) sufA[(size_t)NN * C + c] = 0.f;
        #pragma unroll 8
        for (int e = CHSZ - 1; e >= 0; e--) {
            const int p = p0 + e;
            run = fmaf(A[p], Wh[(size_t)perm[p] * C + c], run);
            sufA[(size_t)p * C + c] = run;
        }
    }
}

// ---------------------------------------------------------------------------
// Kernel 6: per-row combine
// ---------------------------------------------------------------------------
template<int C, bool DO_ELU, int L>
__global__ void k_combine(float* __restrict__ extOut, int rowStride)
{
    const int head = blockIdx.y;
    const float*  __restrict__ s1     = ((L == 0) ? S.s1     : S.s1o)  + head * NN;
    const float*  __restrict__ s2     = ((L == 0) ? S.s2     : S.s2o)  + head * NN;
    const float*  __restrict__ s2s    = ((L == 0) ? S.s2s    : S.s2so) + head * NN;
    const float*  __restrict__ Wh     = ((L == 0) ? S.Wh     : S.Wh2)  + (size_t)head * NN * C;
    const float*  __restrict__ sufA   = ((L == 0) ? S.sufA   : S.sufA2) + (size_t)head * (NN + 1) * C;
    const float*  __restrict__ preB   = ((L == 0) ? S.preB   : S.preB2) + (size_t)head * (NN + 1) * C;
    const double* __restrict__ sufAsc = ((L == 0) ? S.sufAsc : S.sufA2sc) + head * (NN + 1);
    const double* __restrict__ preBsc = ((L == 0) ? S.preBsc : S.preB2sc) + head * (NN + 1);
    float* __restrict__ out = (L == 0) ? S.hcat : extOut;

    constexpr int IPB = 256 / C;
    const int i = blockIdx.x * IPB + threadIdx.x / C;
    const int c = threadIdx.x % C;

    const float s1v = s1[i];
    const float ea  = expf(s1v);
    const float eb  = expf(0.01f * s1v);

    const float target = -s1v;
    int lo = 0, hi = NN;
    while (lo < hi) {
        const int mid = (lo + hi) >> 1;
        if (s2s[mid] < target) lo = mid + 1; else hi = mid;
    }
    const int k = lo;

    const float tii = s1v + s2[i];
    const float wii = expf(tii >= 0.f ? tii : 0.01f * tii);

    const double denom = (double)ea * sufAsc[k] + (double)eb * preBsc[k] - (double)wii;
    const float num = ea * sufA[(size_t)k * C + c]
                    + eb * preB[(size_t)k * C + c]
                    - wii * Wh[(size_t)i * C + c];
    float v = (float)((double)num / denom);
    if (DO_ELU) v = (v > 0.f) ? v : expm1f(v);

    out[(size_t)i * rowStride + head * C + c] = v;
}

// ---------------------------------------------------------------------------
// launch — kernel launches only (10 launches)
// ---------------------------------------------------------------------------
extern "C" void kernel_launch(void* const* d_in, const int* in_sizes, int n_in,
                              void* d_out, int out_size)
{
    const float* x       = (const float*)d_in[0];
    const float* W_heads = (const float*)d_in[3];
    const float* a1h     = (const float*)d_in[4];
    const float* a2h     = (const float*)d_in[5];
    const float* W_out   = (const float*)d_in[6];
    const float* a1o     = (const float*)d_in[7];
    const float* a2o     = (const float*)d_in[8];
    float* out = (float*)d_out;

    // ---- layer 1 (4 heads) ----
    k_gemm1<<<dim3(NN / 64, NH), 256>>>(x, W_heads, a1h, a2h);
    k_sortscan<0><<<NH, 1024>>>();
    k_chunksum<HIDC, 4, 0><<<dim3(NH, NCHUNK / 4), 256>>>();
    k_pass3<HIDC, 4, 0><<<dim3(NH, NCHUNK / 4, 2), 256>>>();
    k_combine<HIDC, true, 0><<<dim3(NN / 4, NH), 256>>>(nullptr, NH * HIDC);

    // ---- layer 2 (output) ----
    k_gemm2<<<NN / 16, 256>>>(W_out, a1o, a2o);
    k_sortscan<1><<<1, 1024>>>();
    k_chunksum<TT, 16, 1><<<dim3(1, NCHUNK / 16), 256>>>();
    k_pass3<TT, 16, 1><<<dim3(1, NCHUNK / 16, 2), 256>>>();
    k_combine<TT, false, 1><<<dim3(NN / 16, 1), 256>>>(out, TT);
}

// round 7
// speedup vs baseline: 1.3274x; 1.0673x over previous
#include <cuda_runtime.h>
#include <math.h>
#include <stddef.h>

// Problem constants
#define NN    4096      // nodes
#define TT    16        // timesteps / out features
#define FF    4         // node features
#define HIDC  64        // hidden per head
#define NH    4         // heads
#define NCHUNK 512
#define CHSZ   8        // NN / NCHUNK
#define CHLOG  3

// ---------------------------------------------------------------------------
// Scratch (static device global)
// ---------------------------------------------------------------------------
struct Scratch {
    // layer 1
    float  Wh[NH * NN * HIDC];
    float  s1[NH * NN];
    float  s2[NH * NN];
    float  s2s[NH * NN];
    int    perm[NH * NN];
    float  A[NH * NN];                 // exp(s2_sorted)
    float  B[NH * NN];                 // exp(0.01*s2_sorted)
    float  csA[NH * NCHUNK * HIDC];    // chunk sums -> exclusive suffix (scanned)
    float  csB[NH * NCHUNK * HIDC];    // chunk sums -> exclusive prefix (scanned)
    double sufAsc[NH * (NN + 1)];
    double preBsc[NH * (NN + 1)];
    float  hcat[NN * NH * HIDC];
    // layer 2
    float  Wh2[NN * TT];
    float  s1o[NN], s2o[NN], s2so[NN];
    int    permo[NN];
    float  Ao[NN], Bo[NN];
    float  csA2[NCHUNK * TT], csB2[NCHUNK * TT];
    double sufA2sc[NN + 1], preB2sc[NN + 1];
};
__device__ Scratch S;

// ---------------------------------------------------------------------------
// Kernel 1: fused transpose(x) -> h, Wh = h @ W[head], s1/s2 dots
// grid (NN/64, NH), block 256
// ---------------------------------------------------------------------------
__global__ void k_gemm1(const float* __restrict__ x,
                        const float* __restrict__ W,
                        const float* __restrict__ a1,
                        const float* __restrict__ a2)
{
    __shared__ float sW[64 * 65];
    __shared__ float sh[64 * 65];

    const int head = blockIdx.y;
    const int n0   = blockIdx.x * 64;
    const int t    = threadIdx.x;

    const float* Wp = W + head * 64 * 64;
    for (int idx = t; idx < 4096; idx += 256)
        sW[(idx >> 6) * 65 + (idx & 63)] = Wp[idx];

    {
        const int dn = t >> 2, f = t & 3;
        #pragma unroll
        for (int tt = 0; tt < TT; tt++)
            sh[dn * 65 + tt * 4 + f] = x[(size_t)tt * NN * FF + (size_t)(n0 + dn) * FF + f];
    }
    __syncthreads();

    const int tc = t & 15, tr = t >> 4;
    float acc[4][4];
    #pragma unroll
    for (int i = 0; i < 4; i++)
        #pragma unroll
        for (int j = 0; j < 4; j++) acc[i][j] = 0.f;

    for (int k = 0; k < 64; k++) {
        float av[4], bv[4];
        #pragma unroll
        for (int i = 0; i < 4; i++) av[i] = sh[(tr + 16 * i) * 65 + k];
        #pragma unroll
        for (int j = 0; j < 4; j++) bv[j] = sW[k * 65 + tc + 16 * j];
        #pragma unroll
        for (int i = 0; i < 4; i++)
            #pragma unroll
            for (int j = 0; j < 4; j++) acc[i][j] = fmaf(av[i], bv[j], acc[i][j]);
    }
    __syncthreads();

    float* __restrict__ WhG = S.Wh;
    #pragma unroll
    for (int i = 0; i < 4; i++) {
        const int r = tr + 16 * i;
        #pragma unroll
        for (int j = 0; j < 4; j++) {
            const int c = tc + 16 * j;
            sW[r * 65 + c] = acc[i][j];
            WhG[((size_t)head * NN + (n0 + r)) * HIDC + c] = acc[i][j];
        }
    }
    __syncthreads();

    if (t < 64) {
        const int r = t;
        const float* ap1 = a1 + head * HIDC;
        const float* ap2 = a2 + head * HIDC;
        float v1 = 0.f, v2 = 0.f;
        #pragma unroll
        for (int c = 0; c < 64; c++) {
            const float w = sW[r * 65 + c];
            v1 = fmaf(w, ap1[c], v1);
            v2 = fmaf(w, ap2[c], v2);
        }
        S.s1[head * NN + n0 + r] = v1;
        S.s2[head * NN + n0 + r] = v2;
    }
}

// ---------------------------------------------------------------------------
// Kernel 2: hcat @ W_out + s1o/s2o.  grid 256, block 256
// ---------------------------------------------------------------------------
__global__ void k_gemm2(const float* __restrict__ Wo,
                        const float* __restrict__ a1,
                        const float* __restrict__ a2)
{
    __shared__ float sW[256 * 17];
    __shared__ float sh2[16 * 257];
    __shared__ float sAcc[16 * 17];

    const float* __restrict__ hcat = S.hcat;
    const int row0 = blockIdx.x * 16;
    const int t    = threadIdx.x;

    for (int idx = t; idx < 4096; idx += 256)
        sW[(idx >> 4) * 17 + (idx & 15)] = Wo[idx];
    #pragma unroll
    for (int r = 0; r < 16; r++)
        sh2[r * 257 + t] = hcat[(size_t)(row0 + r) * 256 + t];
    __syncthreads();

    const int tc = t & 15, tr = t >> 4;
    float acc = 0.f;
    #pragma unroll 8
    for (int k = 0; k < 256; k++)
        acc = fmaf(sh2[tr * 257 + k], sW[k * 17 + tc], acc);

    S.Wh2[(row0 + tr) * TT + tc] = acc;
    sAcc[tr * 17 + tc] = acc;
    __syncthreads();

    if (t < 16) {
        const int r = t;
        float v1 = 0.f, v2 = 0.f;
        #pragma unroll
        for (int c = 0; c < 16; c++) {
            const float w = sAcc[r * 17 + c];
            v1 = fmaf(w, a1[c], v1);
            v2 = fmaf(w, a2[c], v2);
        }
        S.s1o[row0 + r] = v1;
        S.s2o[row0 + r] = v2;
    }
}

// ---------------------------------------------------------------------------
// Kernel 3: bitonic sort (register/shuffle) + exp weights + fused fp64 scans
// 1 block of 1024 per head.
// ---------------------------------------------------------------------------
template<int L>
__global__ void k_sortscan()
{
    const float* __restrict__ s2  = (L == 0) ? S.s2  : S.s2o;
    float*       __restrict__ s2s = (L == 0) ? S.s2s : S.s2so;
    int*         __restrict__ perm= (L == 0) ? S.perm: S.permo;
    float*       __restrict__ A   = (L == 0) ? S.A   : S.Ao;
    float*       __restrict__ B   = (L == 0) ? S.B   : S.Bo;
    double*      __restrict__ sufAsc = ((L == 0) ? S.sufAsc : S.sufA2sc) + blockIdx.x * (NN + 1);
    double*      __restrict__ preBsc = ((L == 0) ? S.preBsc : S.preB2sc) + blockIdx.x * (NN + 1);

    __shared__ float key[NN];
    __shared__ int   sidx[NN];          // reused as double seg[2048] later

    const int base = blockIdx.x * NN;
    const int t    = threadIdx.x;
    const int lane = t & 31;

    float k0[4]; int x0[4];
    #pragma unroll
    for (int m = 0; m < 4; m++) {
        const int i = t + m * 1024;
        k0[m] = s2[base + i];
        x0[m] = i;
    }

    // stages k=2..32 entirely in registers (partner always in-warp)
    #pragma unroll
    for (int k = 2; k <= 32; k <<= 1) {
        #pragma unroll
        for (int j = k >> 1; j >= 1; j >>= 1) {
            #pragma unroll
            for (int m = 0; m < 4; m++) {
                const int i = t + m * 1024;
                const bool up = ((i & k) == 0);
                const float ok = __shfl_xor_sync(0xffffffffu, k0[m], j);
                const int   oi = __shfl_xor_sync(0xffffffffu, x0[m], j);
                const bool lower = ((lane & j) == 0);
                const bool wantMin = (lower == up);
                const bool take = wantMin ? (ok < k0[m]) : (ok > k0[m]);
                if (take) { k0[m] = ok; x0[m] = oi; }
            }
        }
    }
    #pragma unroll
    for (int m = 0; m < 4; m++) {
        const int i = t + m * 1024;
        key[i] = k0[m]; sidx[i] = x0[m];
    }
    __syncthreads();

    // stages k=64..4096: smem passes down to j=32, then in-warp shuffle tail
    for (int k = 64; k <= NN; k <<= 1) {
        for (int j = k >> 1; j >= 32; j >>= 1) {
            #pragma unroll
            for (int m = 0; m < 4; m++) {
                const int i = t + m * 1024;
                const int ixj = i ^ j;
                if (ixj > i) {
                    const bool up = ((i & k) == 0);
                    const float a = key[i], b = key[ixj];
                    if ((a > b) == up) {
                        key[i] = b; key[ixj] = a;
                        const int tmp = sidx[i]; sidx[i] = sidx[ixj]; sidx[ixj] = tmp;
                    }
                }
            }
            __syncthreads();
        }
        #pragma unroll
        for (int m = 0; m < 4; m++) {
            const int i = t + m * 1024;
            k0[m] = key[i]; x0[m] = sidx[i];
        }
        #pragma unroll
        for (int j = 16; j >= 1; j >>= 1) {
            #pragma unroll
            for (int m = 0; m < 4; m++) {
                const int i = t + m * 1024;
                const bool up = ((i & k) == 0);
                const float ok = __shfl_xor_sync(0xffffffffu, k0[m], j);
                const int   oi = __shfl_xor_sync(0xffffffffu, x0[m], j);
                const bool lower = ((lane & j) == 0);
                const bool wantMin = (lower == up);
                const bool take = wantMin ? (ok < k0[m]) : (ok > k0[m]);
                if (take) { k0[m] = ok; x0[m] = oi; }
            }
        }
        #pragma unroll
        for (int m = 0; m < 4; m++) {
            const int i = t + m * 1024;
            key[i] = k0[m]; sidx[i] = x0[m];
        }
        __syncthreads();
    }

    // write sorted keys / perm / exp weights from registers
    #pragma unroll
    for (int m = 0; m < 4; m++) {
        const int i = t + m * 1024;
        const float v = k0[m];
        s2s[base + i]  = v;
        perm[base + i] = x0[m];
        A[base + i]    = expf(v);
        B[base + i]    = expf(0.01f * v);
    }
    __syncthreads();

    // fused scalar scans (fp64): thread t owns positions 4t..4t+3
    double* seg = (double*)sidx;     // 2048 doubles
    float av[4], bv[4];
    double la = 0.0, lb = 0.0;
    #pragma unroll
    for (int e = 0; e < 4; e++) {
        const float v = key[4 * t + e];
        av[e] = expf(v); bv[e] = expf(0.01f * v);
        la += (double)av[e]; lb += (double)bv[e];
    }
    seg[t] = la; seg[1024 + t] = lb;
    __syncthreads();

    for (int d = 1; d < 1024; d <<= 1) {
        double va = 0.0, vb = 0.0;
        if (t >= d) { va = seg[t - d]; vb = seg[1024 + t - d]; }
        __syncthreads();
        seg[t] += va; seg[1024 + t] += vb;
        __syncthreads();
    }

    const double exA = seg[t] - la;
    const double exB = seg[1024 + t] - lb;
    const double totA = seg[1023];
    const double totB = seg[2047];

    double runB = exB, runA = exA;
    #pragma unroll
    for (int e = 0; e < 4; e++) {
        const int p = 4 * t + e;
        preBsc[p] = runB;        runB += (double)bv[e];
        sufAsc[p] = totA - runA; runA += (double)av[e];
    }
    if (t == 1023) { preBsc[NN] = totB; sufAsc[NN] = 0.0; }
}

// ---------------------------------------------------------------------------
// Kernel 4: per-chunk fp32 column sums of A*Wh[perm] and B*Wh[perm]
// chains are CHSZ=8 long; fully unrolled.
// ---------------------------------------------------------------------------
template<int C, int CPB, int L>
__global__ void k_chunksum()
{
    const int head = blockIdx.x;
    const float* __restrict__ Wh   = ((L == 0) ? S.Wh   : S.Wh2) + (size_t)head * NN * C;
    const int*   __restrict__ perm = ((L == 0) ? S.perm : S.permo) + head * NN;
    const float* __restrict__ A    = ((L == 0) ? S.A    : S.Ao)   + head * NN;
    const float* __restrict__ B    = ((L == 0) ? S.B    : S.Bo)   + head * NN;
    float*       __restrict__ csA  = ((L == 0) ? S.csA  : S.csA2) + (size_t)head * NCHUNK * C;
    float*       __restrict__ csB  = ((L == 0) ? S.csB  : S.csB2) + (size_t)head * NCHUNK * C;

    const int c = threadIdx.x % C;
    const int q = blockIdx.y * CPB + threadIdx.x / C;
    const int p0 = q * CHSZ;
    float sa = 0.f, sb = 0.f;
    #pragma unroll
    for (int e = 0; e < CHSZ; e++) {
        const int p = p0 + e;
        const float w = Wh[(size_t)perm[p] * C + c];
        sa = fmaf(A[p], w, sa);
        sb = fmaf(B[p], w, sb);
    }
    csA[q * C + c] = sa;
    csB[q * C + c] = sb;
}

// ---------------------------------------------------------------------------
// Kernel 5: warp-parallel in-place scan of chunk sums.
// csB -> exclusive prefix over chunks; csA -> exclusive suffix over chunks.
// One warp per (head, channel) column; lane owns 16 consecutive chunks.
// ---------------------------------------------------------------------------
template<int C, int NHL, int L>
__global__ void k_chunkscan()
{
    const int wid = (blockIdx.x * blockDim.x + threadIdx.x) >> 5;
    const int lane = threadIdx.x & 31;
    if (wid >= NHL * C) return;
    const int head = wid / C;
    const int c    = wid % C;

    float* __restrict__ csA = ((L == 0) ? S.csA : S.csA2) + (size_t)head * NCHUNK * C + c;
    float* __restrict__ csB = ((L == 0) ? S.csB : S.csB2) + (size_t)head * NCHUNK * C + c;

    constexpr int PER = NCHUNK / 32;   // 16 chunks per lane
    float va[PER], vb[PER];
    float sa = 0.f, sb = 0.f;
    #pragma unroll
    for (int i = 0; i < PER; i++) {
        va[i] = csA[(lane * PER + i) * C];
        vb[i] = csB[(lane * PER + i) * C];
        sa += va[i]; sb += vb[i];
    }

    // inclusive warp scans of lane totals
    float incA = sa, incB = sb;
    #pragma unroll
    for (int d = 1; d < 32; d <<= 1) {
        const float ta = __shfl_up_sync(0xffffffffu, incA, d);
        const float tb = __shfl_up_sync(0xffffffffu, incB, d);
        if (lane >= d) { incA += ta; incB += tb; }
    }
    const float totA = __shfl_sync(0xffffffffu, incA, 31);
    const float exclB_lane = incB - sb;          // prefix of lanes < lane
    const float sufA_lane  = totA - incA;        // sum of lanes > lane

    // csB: exclusive prefix
    float run = exclB_lane;
    #pragma unroll
    for (int i = 0; i < PER; i++) {
        const float v = vb[i];
        csB[(lane * PER + i) * C] = run;
        run += v;
    }
    // csA: exclusive suffix
    run = sufA_lane;
    #pragma unroll
    for (int i = PER - 1; i >= 0; i--) {
        run += va[i];
        // store exclusive-of-self suffix: sum over chunks > q
        csA[(lane * PER + i) * C] = run - va[i];
    }
}

// ---------------------------------------------------------------------------
// Kernel 6: per-row combine with on-demand in-chunk partial sums.
// block 256 = (256/C) rows x C channels.
// ---------------------------------------------------------------------------
template<int C, bool DO_ELU, int L>
__global__ void k_combine(float* __restrict__ extOut, int rowStride)
{
    const int head = blockIdx.y;
    const float*  __restrict__ s1     = ((L == 0) ? S.s1     : S.s1o)  + head * NN;
    const float*  __restrict__ s2     = ((L == 0) ? S.s2     : S.s2o)  + head * NN;
    const float*  __restrict__ s2s    = ((L == 0) ? S.s2s    : S.s2so) + head * NN;
    const int*    __restrict__ perm   = ((L == 0) ? S.perm   : S.permo) + head * NN;
    const float*  __restrict__ A      = ((L == 0) ? S.A      : S.Ao)   + head * NN;
    const float*  __restrict__ B      = ((L == 0) ? S.B      : S.Bo)   + head * NN;
    const float*  __restrict__ Wh     = ((L == 0) ? S.Wh     : S.Wh2)  + (size_t)head * NN * C;
    const float*  __restrict__ csAs   = ((L == 0) ? S.csA    : S.csA2) + (size_t)head * NCHUNK * C;
    const float*  __restrict__ csBs   = ((L == 0) ? S.csB    : S.csB2) + (size_t)head * NCHUNK * C;
    const double* __restrict__ sufAsc = ((L == 0) ? S.sufAsc : S.sufA2sc) + head * (NN + 1);
    const double* __restrict__ preBsc = ((L == 0) ? S.preBsc : S.preB2sc) + head * (NN + 1);
    float* __restrict__ out = (L == 0) ? S.hcat : extOut;

    constexpr int IPB = 256 / C;
    const int i = blockIdx.x * IPB + threadIdx.x / C;
    const int c = threadIdx.x % C;

    const float s1v = s1[i];
    const float ea  = expf(s1v);
    const float eb  = expf(0.01f * s1v);

    // lower_bound(s2s, -s1v)
    const float target = -s1v;
    int lo = 0, hi = NN;
    while (lo < hi) {
        const int mid = (lo + hi) >> 1;
        if (s2s[mid] < target) lo = mid + 1; else hi = mid;
    }
    const int k = lo;
    const int q = min(k >> CHLOG, NCHUNK - 1);

    // accumulators seeded with scanned chunk offsets
    float accA = csAs[q * C + c];     // sum over chunks > q (A-weighted)
    float accB = csBs[q * C + c];     // sum over chunks < q (B-weighted)

    // in-chunk partial: positions p in [q*8, q*8+8): p>=k -> A side, else B side
    const int p0 = q << CHLOG;
    #pragma unroll
    for (int e = 0; e < CHSZ; e++) {
        const int p = p0 + e;
        const float w = Wh[(size_t)perm[p] * C + c];
        if (p >= k) accA = fmaf(A[p], w, accA);
        else        accB = fmaf(B[p], w, accB);
    }

    const float tii = s1v + s2[i];
    const float wii = expf(tii >= 0.f ? tii : 0.01f * tii);

    const double denom = (double)ea * sufAsc[k] + (double)eb * preBsc[k] - (double)wii;
    const float num = ea * accA + eb * accB - wii * Wh[(size_t)i * C + c];
    float v = (float)((double)num / denom);
    if (DO_ELU) v = (v > 0.f) ? v : expm1f(v);

    out[(size_t)i * rowStride + head * C + c] = v;
}

// ---------------------------------------------------------------------------
// launch — kernel launches only (10 launches)
// ---------------------------------------------------------------------------
extern "C" void kernel_launch(void* const* d_in, const int* in_sizes, int n_in,
                              void* d_out, int out_size)
{
    const float* x       = (const float*)d_in[0];
    const float* W_heads = (const float*)d_in[3];
    const float* a1h     = (const float*)d_in[4];
    const float* a2h     = (const float*)d_in[5];
    const float* W_out   = (const float*)d_in[6];
    const float* a1o     = (const float*)d_in[7];
    const float* a2o     = (const float*)d_in[8];
    float* out = (float*)d_out;

    // ---- layer 1 (4 heads) ----
    k_gemm1<<<dim3(NN / 64, NH), 256>>>(x, W_heads, a1h, a2h);
    k_sortscan<0><<<NH, 1024>>>();
    k_chunksum<HIDC, 4, 0><<<dim3(NH, NCHUNK / 4), 256>>>();
    k_chunkscan<HIDC, NH, 0><<<(NH * HIDC * 32 + 255) / 256, 256>>>();
    k_combine<HIDC, true, 0><<<dim3(NN / 4, NH), 256>>>(nullptr, NH * HIDC);

    // ---- layer 2 (output) ----
    k_gemm2<<<NN / 16, 256>>>(W_out, a1o, a2o);
    k_sortscan<1><<<1, 1024>>>();
    k_chunksum<TT, 16, 1><<<dim3(1, NCHUNK / 16), 256>>>();
    k_chunkscan<TT, 1, 1><<<(TT * 32 + 255) / 256, 256>>>();
    k_combine<TT, false, 1><<<dim3(NN / 16, 1), 256>>>(out, TT);
}

// round 8
// speedup vs baseline: 1.3894x; 1.0467x over previous
#include <cuda_runtime.h>
#include <math.h>
#include <stddef.h>

// Problem constants
#define NN    4096      // nodes
#define TT    16        // timesteps / out features
#define FF    4         // node features
#define HIDC  64        // hidden per head
#define NH    4         // heads
#define NCHUNK 512
#define CHSZ   8        // NN / NCHUNK
#define CHLOG  3

// ---------------------------------------------------------------------------
// Scratch (static device global)
// ---------------------------------------------------------------------------
struct Scratch {
    // layer 1
    float  Wh[NH * NN * HIDC];
    float  s1[NH * NN];
    float  s2[NH * NN];
    float  s2s[NH * NN];
    int    perm[NH * NN];
    float  A[NH * NN];                 // exp(s2_sorted)
    float  B[NH * NN];                 // exp(0.01*s2_sorted)
    float  csA[NH * NCHUNK * HIDC];    // chunk sums -> exclusive suffix (scanned)
    float  csB[NH * NCHUNK * HIDC];    // chunk sums -> exclusive prefix (scanned)
    double sufAsc[NH * (NN + 1)];
    double preBsc[NH * (NN + 1)];
    float  hcat[NN * NH * HIDC];
    // layer 2
    float  Wh2[NN * TT];
    float  s1o[NN], s2o[NN], s2so[NN];
    int    permo[NN];
    float  Ao[NN], Bo[NN];
    float  csA2[NCHUNK * TT], csB2[NCHUNK * TT];
    double sufA2sc[NN + 1], preB2sc[NN + 1];
};
__device__ Scratch S;

// ---------------------------------------------------------------------------
// Kernel 1: fused transpose(x) -> h, Wh = h @ W[head], s1/s2 dots
// grid (NN/64, NH), block 256
// ---------------------------------------------------------------------------
__global__ void k_gemm1(const float* __restrict__ x,
                        const float* __restrict__ W,
                        const float* __restrict__ a1,
                        const float* __restrict__ a2)
{
    __shared__ float sW[64 * 65];
    __shared__ float sh[64 * 65];

    const int head = blockIdx.y;
    const int n0   = blockIdx.x * 64;
    const int t    = threadIdx.x;

    const float* Wp = W + head * 64 * 64;
    for (int idx = t; idx < 4096; idx += 256)
        sW[(idx >> 6) * 65 + (idx & 63)] = Wp[idx];

    {
        const int dn = t >> 2, f = t & 3;
        #pragma unroll
        for (int tt = 0; tt < TT; tt++)
            sh[dn * 65 + tt * 4 + f] = x[(size_t)tt * NN * FF + (size_t)(n0 + dn) * FF + f];
    }
    __syncthreads();

    const int tc = t & 15, tr = t >> 4;
    float acc[4][4];
    #pragma unroll
    for (int i = 0; i < 4; i++)
        #pragma unroll
        for (int j = 0; j < 4; j++) acc[i][j] = 0.f;

    for (int k = 0; k < 64; k++) {
        float av[4], bv[4];
        #pragma unroll
        for (int i = 0; i < 4; i++) av[i] = sh[(tr + 16 * i) * 65 + k];
        #pragma unroll
        for (int j = 0; j < 4; j++) bv[j] = sW[k * 65 + tc + 16 * j];
        #pragma unroll
        for (int i = 0; i < 4; i++)
            #pragma unroll
            for (int j = 0; j < 4; j++) acc[i][j] = fmaf(av[i], bv[j], acc[i][j]);
    }
    __syncthreads();

    float* __restrict__ WhG = S.Wh;
    #pragma unroll
    for (int i = 0; i < 4; i++) {
        const int r = tr + 16 * i;
        #pragma unroll
        for (int j = 0; j < 4; j++) {
            const int c = tc + 16 * j;
            sW[r * 65 + c] = acc[i][j];
            WhG[((size_t)head * NN + (n0 + r)) * HIDC + c] = acc[i][j];
        }
    }
    __syncthreads();

    if (t < 64) {
        const int r = t;
        const float* ap1 = a1 + head * HIDC;
        const float* ap2 = a2 + head * HIDC;
        float v1 = 0.f, v2 = 0.f;
        #pragma unroll
        for (int c = 0; c < 64; c++) {
            const float w = sW[r * 65 + c];
            v1 = fmaf(w, ap1[c], v1);
            v2 = fmaf(w, ap2[c], v2);
        }
        S.s1[head * NN + n0 + r] = v1;
        S.s2[head * NN + n0 + r] = v2;
    }
}

// ---------------------------------------------------------------------------
// Kernel 2: hcat @ W_out + s1o/s2o.  grid 256, block 256
// ---------------------------------------------------------------------------
__global__ void k_gemm2(const float* __restrict__ Wo,
                        const float* __restrict__ a1,
                        const float* __restrict__ a2)
{
    __shared__ float sW[256 * 17];
    __shared__ float sh2[16 * 257];
    __shared__ float sAcc[16 * 17];

    const float* __restrict__ hcat = S.hcat;
    const int row0 = blockIdx.x * 16;
    const int t    = threadIdx.x;

    for (int idx = t; idx < 4096; idx += 256)
        sW[(idx >> 4) * 17 + (idx & 15)] = Wo[idx];
    #pragma unroll
    for (int r = 0; r < 16; r++)
        sh2[r * 257 + t] = hcat[(size_t)(row0 + r) * 256 + t];
    __syncthreads();

    const int tc = t & 15, tr = t >> 4;
    float acc = 0.f;
    #pragma unroll 8
    for (int k = 0; k < 256; k++)
        acc = fmaf(sh2[tr * 257 + k], sW[k * 17 + tc], acc);

    S.Wh2[(row0 + tr) * TT + tc] = acc;
    sAcc[tr * 17 + tc] = acc;
    __syncthreads();

    if (t < 16) {
        const int r = t;
        float v1 = 0.f, v2 = 0.f;
        #pragma unroll
        for (int c = 0; c < 16; c++) {
            const float w = sAcc[r * 17 + c];
            v1 = fmaf(w, a1[c], v1);
            v2 = fmaf(w, a2[c], v2);
        }
        S.s1o[row0 + r] = v1;
        S.s2o[row0 + r] = v2;
    }
}

// ---------------------------------------------------------------------------
// Kernel 3: bitonic sort (register/shuffle) + exp weights + fused fp64 scans
// 1 block of 1024 per head.
// ---------------------------------------------------------------------------
template<int L>
__global__ void k_sortscan()
{
    const float* __restrict__ s2  = (L == 0) ? S.s2  : S.s2o;
    float*       __restrict__ s2s = (L == 0) ? S.s2s : S.s2so;
    int*         __restrict__ perm= (L == 0) ? S.perm: S.permo;
    float*       __restrict__ A   = (L == 0) ? S.A   : S.Ao;
    float*       __restrict__ B   = (L == 0) ? S.B   : S.Bo;
    double*      __restrict__ sufAsc = ((L == 0) ? S.sufAsc : S.sufA2sc) + blockIdx.x * (NN + 1);
    double*      __restrict__ preBsc = ((L == 0) ? S.preBsc : S.preB2sc) + blockIdx.x * (NN + 1);

    __shared__ float key[NN];
    __shared__ int   sidx[NN];          // reused as double seg[2048] later

    const int base = blockIdx.x * NN;
    const int t    = threadIdx.x;
    const int lane = t & 31;

    float k0[4]; int x0[4];
    #pragma unroll
    for (int m = 0; m < 4; m++) {
        const int i = t + m * 1024;
        k0[m] = s2[base + i];
        x0[m] = i;
    }

    // stages k=2..32 entirely in registers (partner always in-warp)
    #pragma unroll
    for (int k = 2; k <= 32; k <<= 1) {
        #pragma unroll
        for (int j = k >> 1; j >= 1; j >>= 1) {
            #pragma unroll
            for (int m = 0; m < 4; m++) {
                const int i = t + m * 1024;
                const bool up = ((i & k) == 0);
                const float ok = __shfl_xor_sync(0xffffffffu, k0[m], j);
                const int   oi = __shfl_xor_sync(0xffffffffu, x0[m], j);
                const bool lower = ((lane & j) == 0);
                const bool wantMin = (lower == up);
                const bool take = wantMin ? (ok < k0[m]) : (ok > k0[m]);
                if (take) { k0[m] = ok; x0[m] = oi; }
            }
        }
    }
    #pragma unroll
    for (int m = 0; m < 4; m++) {
        const int i = t + m * 1024;
        key[i] = k0[m]; sidx[i] = x0[m];
    }
    __syncthreads();

    // stages k=64..4096: smem passes down to j=32, then in-warp shuffle tail
    for (int k = 64; k <= NN; k <<= 1) {
        for (int j = k >> 1; j >= 32; j >>= 1) {
            #pragma unroll
            for (int m = 0; m < 4; m++) {
                const int i = t + m * 1024;
                const int ixj = i ^ j;
                if (ixj > i) {
                    const bool up = ((i & k) == 0);
                    const float a = key[i], b = key[ixj];
                    if ((a > b) == up) {
                        key[i] = b; key[ixj] = a;
                        const int tmp = sidx[i]; sidx[i] = sidx[ixj]; sidx[ixj] = tmp;
                    }
                }
            }
            __syncthreads();
        }
        #pragma unroll
        for (int m = 0; m < 4; m++) {
            const int i = t + m * 1024;
            k0[m] = key[i]; x0[m] = sidx[i];
        }
        #pragma unroll
        for (int j = 16; j >= 1; j >>= 1) {
            #pragma unroll
            for (int m = 0; m < 4; m++) {
                const int i = t + m * 1024;
                const bool up = ((i & k) == 0);
                const float ok = __shfl_xor_sync(0xffffffffu, k0[m], j);
                const int   oi = __shfl_xor_sync(0xffffffffu, x0[m], j);
                const bool lower = ((lane & j) == 0);
                const bool wantMin = (lower == up);
                const bool take = wantMin ? (ok < k0[m]) : (ok > k0[m]);
                if (take) { k0[m] = ok; x0[m] = oi; }
            }
        }
        #pragma unroll
        for (int m = 0; m < 4; m++) {
            const int i = t + m * 1024;
            key[i] = k0[m]; sidx[i] = x0[m];
        }
        __syncthreads();
    }

    // write sorted keys / perm / exp weights from registers
    #pragma unroll
    for (int m = 0; m < 4; m++) {
        const int i = t + m * 1024;
        const float v = k0[m];
        s2s[base + i]  = v;
        perm[base + i] = x0[m];
        A[base + i]    = expf(v);
        B[base + i]    = expf(0.01f * v);
    }
    __syncthreads();

    // fused scalar scans (fp64): thread t owns positions 4t..4t+3
    double* seg = (double*)sidx;     // 2048 doubles
    float av[4], bv[4];
    double la = 0.0, lb = 0.0;
    #pragma unroll
    for (int e = 0; e < 4; e++) {
        const float v = key[4 * t + e];
        av[e] = expf(v); bv[e] = expf(0.01f * v);
        la += (double)av[e]; lb += (double)bv[e];
    }
    seg[t] = la; seg[1024 + t] = lb;
    __syncthreads();

    for (int d = 1; d < 1024; d <<= 1) {
        double va = 0.0, vb = 0.0;
        if (t >= d) { va = seg[t - d]; vb = seg[1024 + t - d]; }
        __syncthreads();
        seg[t] += va; seg[1024 + t] += vb;
        __syncthreads();
    }

    const double exA = seg[t] - la;
    const double exB = seg[1024 + t] - lb;
    const double totA = seg[1023];
    const double totB = seg[2047];

    double runB = exB, runA = exA;
    #pragma unroll
    for (int e = 0; e < 4; e++) {
        const int p = 4 * t + e;
        preBsc[p] = runB;        runB += (double)bv[e];
        sufAsc[p] = totA - runA; runA += (double)av[e];
    }
    if (t == 1023) { preBsc[NN] = totB; sufAsc[NN] = 0.0; }
}

// ---------------------------------------------------------------------------
// Kernel 4: per-chunk fp32 column sums of A*Wh[perm] and B*Wh[perm]
// ---------------------------------------------------------------------------
template<int C, int CPB, int L>
__global__ void k_chunksum()
{
    const int head = blockIdx.x;
    const float* __restrict__ Wh   = ((L == 0) ? S.Wh   : S.Wh2) + (size_t)head * NN * C;
    const int*   __restrict__ perm = ((L == 0) ? S.perm : S.permo) + head * NN;
    const float* __restrict__ A    = ((L == 0) ? S.A    : S.Ao)   + head * NN;
    const float* __restrict__ B    = ((L == 0) ? S.B    : S.Bo)   + head * NN;
    float*       __restrict__ csA  = ((L == 0) ? S.csA  : S.csA2) + (size_t)head * NCHUNK * C;
    float*       __restrict__ csB  = ((L == 0) ? S.csB  : S.csB2) + (size_t)head * NCHUNK * C;

    const int c = threadIdx.x % C;
    const int q = blockIdx.y * CPB + threadIdx.x / C;
    const int p0 = q * CHSZ;
    float sa = 0.f, sb = 0.f;
    #pragma unroll
    for (int e = 0; e < CHSZ; e++) {
        const int p = p0 + e;
        const float w = Wh[(size_t)perm[p] * C + c];
        sa = fmaf(A[p], w, sa);
        sb = fmaf(B[p], w, sb);
    }
    csA[q * C + c] = sa;
    csB[q * C + c] = sb;
}

// ---------------------------------------------------------------------------
// Kernel 5: smem-staged scan of chunk sums.
// Block = (head, group of 8 channels); 256 threads = 8 warps; warp w scans
// channel c0+w. csB -> exclusive prefix; csA -> exclusive suffix.
// ---------------------------------------------------------------------------
#define SCAN_G 8
template<int C, int L>
__global__ void k_chunkscan()
{
    __shared__ float sA[NCHUNK * (SCAN_G + 1)];
    __shared__ float sB[NCHUNK * (SCAN_G + 1)];

    const int head = blockIdx.x;
    const int c0   = blockIdx.y * SCAN_G;
    float* __restrict__ csA = ((L == 0) ? S.csA : S.csA2) + (size_t)head * NCHUNK * C;
    float* __restrict__ csB = ((L == 0) ? S.csB : S.csB2) + (size_t)head * NCHUNK * C;

    const int t    = threadIdx.x;
    const int lane = t & 31;
    const int w    = t >> 5;           // warp id = local channel

    // coalesced-ish load: 8 contiguous channels per q
    for (int idx = t; idx < NCHUNK * SCAN_G; idx += 256) {
        const int q  = idx >> 3;
        const int cl = idx & 7;
        sA[q * (SCAN_G + 1) + cl] = csA[q * C + c0 + cl];
        sB[q * (SCAN_G + 1) + cl] = csB[q * C + c0 + cl];
    }
    __syncthreads();

    // warp w scans channel w: 16 carry-chained warp scans over q = lane + 32*i
    {
        // B: exclusive prefix (ascending q)
        float carry = 0.f;
        #pragma unroll
        for (int i = 0; i < NCHUNK / 32; i++) {
            const int q = lane + 32 * i;
            const float v = sB[q * (SCAN_G + 1) + w];
            float inc = v;
            #pragma unroll
            for (int d = 1; d < 32; d <<= 1) {
                const float tv = __shfl_up_sync(0xffffffffu, inc, d);
                if (lane >= d) inc += tv;
            }
            sB[q * (SCAN_G + 1) + w] = carry + inc - v;
            carry += __shfl_sync(0xffffffffu, inc, 31);
        }
        // A: exclusive suffix (descending q)
        carry = 0.f;
        #pragma unroll
        for (int i = NCHUNK / 32 - 1; i >= 0; i--) {
            const int q = lane + 32 * i;
            const float v = sA[q * (SCAN_G + 1) + w];
            float inc = v;   // inclusive suffix within round (lanes >= lane)
            #pragma unroll
            for (int d = 1; d < 32; d <<= 1) {
                const float tv = __shfl_down_sync(0xffffffffu, inc, d);
                if (lane < 32 - d) inc += tv;
            }
            sA[q * (SCAN_G + 1) + w] = carry + inc - v;
            carry += __shfl_sync(0xffffffffu, inc, 0);
        }
    }
    __syncthreads();

    for (int idx = t; idx < NCHUNK * SCAN_G; idx += 256) {
        const int q  = idx >> 3;
        const int cl = idx & 7;
        csA[q * C + c0 + cl] = sA[q * (SCAN_G + 1) + cl];
        csB[q * C + c0 + cl] = sB[q * (SCAN_G + 1) + cl];
    }
}

// ---------------------------------------------------------------------------
// Kernel 6: per-row combine; row-level scalars computed once per row and
// shared via smem.  block 256 = IPB rows x C channels.
// ---------------------------------------------------------------------------
template<int C, bool DO_ELU, int L>
__global__ void k_combine(float* __restrict__ extOut, int rowStride)
{
    constexpr int IPB = 256 / C;
    __shared__ int    skk[IPB];
    __shared__ float  sEa[IPB], sEb[IPB], sWii[IPB];
    __shared__ double sRd[IPB];

    const int head = blockIdx.y;
    const float*  __restrict__ s1     = ((L == 0) ? S.s1     : S.s1o)  + head * NN;
    const float*  __restrict__ s2     = ((L == 0) ? S.s2     : S.s2o)  + head * NN;
    const float*  __restrict__ s2s    = ((L == 0) ? S.s2s    : S.s2so) + head * NN;
    const int*    __restrict__ perm   = ((L == 0) ? S.perm   : S.permo) + head * NN;
    const float*  __restrict__ A      = ((L == 0) ? S.A      : S.Ao)   + head * NN;
    const float*  __restrict__ B      = ((L == 0) ? S.B      : S.Bo)   + head * NN;
    const float*  __restrict__ Wh     = ((L == 0) ? S.Wh     : S.Wh2)  + (size_t)head * NN * C;
    const float*  __restrict__ csAs   = ((L == 0) ? S.csA    : S.csA2) + (size_t)head * NCHUNK * C;
    const float*  __restrict__ csBs   = ((L == 0) ? S.csB    : S.csB2) + (size_t)head * NCHUNK * C;
    const double* __restrict__ sufAsc = ((L == 0) ? S.sufAsc : S.sufA2sc) + head * (NN + 1);
    const double* __restrict__ preBsc = ((L == 0) ? S.preBsc : S.preB2sc) + head * (NN + 1);
    float* __restrict__ out = (L == 0) ? S.hcat : extOut;

    const int r = threadIdx.x / C;
    const int i = blockIdx.x * IPB + r;
    const int c = threadIdx.x % C;

    if (c == 0) {
        const float s1v = s1[i];
        const float ea  = expf(s1v);
        const float eb  = expf(0.01f * s1v);
        const float target = -s1v;
        int lo = 0, hi = NN;
        while (lo < hi) {
            const int mid = (lo + hi) >> 1;
            if (s2s[mid] < target) lo = mid + 1; else hi = mid;
        }
        const float tii = s1v + s2[i];
        const float wii = expf(tii >= 0.f ? tii : 0.01f * tii);
        const double denom = (double)ea * sufAsc[lo] + (double)eb * preBsc[lo] - (double)wii;
        skk[r] = lo;  sEa[r] = ea;  sEb[r] = eb;  sWii[r] = wii;
        sRd[r] = 1.0 / denom;
    }
    __syncthreads();

    const int   k   = skk[r];
    const float ea  = sEa[r];
    const float eb  = sEb[r];
    const float wii = sWii[r];
    const double rd = sRd[r];
    const int q = min(k >> CHLOG, NCHUNK - 1);

    float accA = csAs[q * C + c];     // sum over chunks > q (A-weighted)
    float accB = csBs[q * C + c];     // sum over chunks < q (B-weighted)

    const int p0 = q << CHLOG;
    #pragma unroll
    for (int e = 0; e < CHSZ; e++) {
        const int p = p0 + e;
        const float w = Wh[(size_t)perm[p] * C + c];
        if (p >= k) accA = fmaf(A[p], w, accA);
        else        accB = fmaf(B[p], w, accB);
    }

    const float num = ea * accA + eb * accB - wii * Wh[(size_t)i * C + c];
    float v = (float)((double)num * rd);
    if (DO_ELU) v = (v > 0.f) ? v : expm1f(v);

    out[(size_t)i * rowStride + head * C + c] = v;
}

// ---------------------------------------------------------------------------
// launch — kernel launches only (10 launches)
// ---------------------------------------------------------------------------
extern "C" void kernel_launch(void* const* d_in, const int* in_sizes, int n_in,
                              void* d_out, int out_size)
{
    const float* x       = (const float*)d_in[0];
    const float* W_heads = (const float*)d_in[3];
    const float* a1h     = (const float*)d_in[4];
    const float* a2h     = (const float*)d_in[5];
    const float* W_out   = (const float*)d_in[6];
    const float* a1o     = (const float*)d_in[7];
    const float* a2o     = (const float*)d_in[8];
    float* out = (float*)d_out;

    // ---- layer 1 (4 heads) ----
    k_gemm1<<<dim3(NN / 64, NH), 256>>>(x, W_heads, a1h, a2h);
    k_sortscan<0><<<NH, 1024>>>();
    k_chunksum<HIDC, 4, 0><<<dim3(NH, NCHUNK / 4), 256>>>();
    k_chunkscan<HIDC, 0><<<dim3(NH, HIDC / SCAN_G), 256>>>();
    k_combine<HIDC, true, 0><<<dim3(NN / 4, NH), 256>>>(nullptr, NH * HIDC);

    // ---- layer 2 (output) ----
    k_gemm2<<<NN / 16, 256>>>(W_out, a1o, a2o);
    k_sortscan<1><<<1, 1024>>>();
    k_chunksum<TT, 16, 1><<<dim3(1, NCHUNK / 16), 256>>>();
    k_chunkscan<TT, 1><<<dim3(1, TT / SCAN_G), 256>>>();
    k_combine<TT, false, 1><<<dim3(NN / 16, 1), 256>>>(out, TT);
}

// round 9
// speedup vs baseline: 1.4054x; 1.0116x over previous
#include <cuda_runtime.h>
#include <math.h>
#include <stddef.h>

// Problem constants
#define NN    4096      // nodes
#define TT    16        // timesteps / out features
#define FF    4         // node features
#define HIDC  64        // hidden per head
#define NH    4         // heads
#define NCHUNK 512
#define CHSZ   8        // NN / NCHUNK
#define CHLOG  3

// ---------------------------------------------------------------------------
// Scratch (static device global)
// ---------------------------------------------------------------------------
struct Scratch {
    // layer 1
    float  Wh[NH * NN * HIDC];
    float  s1[NH * NN];
    float  s2[NH * NN];
    float  s2s[NH * NN];
    int    perm[NH * NN];
    float  A[NH * NN];                 // exp(s2_sorted)
    float  B[NH * NN];                 // exp(0.01*s2_sorted)
    float  csA[NH * NCHUNK * HIDC];    // chunk sums -> exclusive suffix (scanned)
    float  csB[NH * NCHUNK * HIDC];    // chunk sums -> exclusive prefix (scanned)
    double sufAsc[NH * (NN + 1)];
    double preBsc[NH * (NN + 1)];
    float  hcat[NN * NH * HIDC];
    // layer 2
    float  Wh2[NN * TT];
    float  s1o[NN], s2o[NN], s2so[NN];
    int    permo[NN];
    float  Ao[NN], Bo[NN];
    float  csA2[NCHUNK * TT], csB2[NCHUNK * TT];
    double sufA2sc[NN + 1], preB2sc[NN + 1];
};
__device__ Scratch S;

// ---------------------------------------------------------------------------
// Kernel 1: fused transpose(x) -> h, Wh = h @ W[head], s1/s2 dots
// grid (NN/64, NH), block 256
// ---------------------------------------------------------------------------
__global__ void k_gemm1(const float* __restrict__ x,
                        const float* __restrict__ W,
                        const float* __restrict__ a1,
                        const float* __restrict__ a2)
{
    __shared__ float sW[64 * 65];
    __shared__ float sh[64 * 65];

    const int head = blockIdx.y;
    const int n0   = blockIdx.x * 64;
    const int t    = threadIdx.x;

    const float* Wp = W + head * 64 * 64;
    for (int idx = t; idx < 4096; idx += 256)
        sW[(idx >> 6) * 65 + (idx & 63)] = Wp[idx];

    {
        const int dn = t >> 2, f = t & 3;
        #pragma unroll
        for (int tt = 0; tt < TT; tt++)
            sh[dn * 65 + tt * 4 + f] = x[(size_t)tt * NN * FF + (size_t)(n0 + dn) * FF + f];
    }
    __syncthreads();

    const int tc = t & 15, tr = t >> 4;
    float acc[4][4];
    #pragma unroll
    for (int i = 0; i < 4; i++)
        #pragma unroll
        for (int j = 0; j < 4; j++) acc[i][j] = 0.f;

    for (int k = 0; k < 64; k++) {
        float av[4], bv[4];
        #pragma unroll
        for (int i = 0; i < 4; i++) av[i] = sh[(tr + 16 * i) * 65 + k];
        #pragma unroll
        for (int j = 0; j < 4; j++) bv[j] = sW[k * 65 + tc + 16 * j];
        #pragma unroll
        for (int i = 0; i < 4; i++)
            #pragma unroll
            for (int j = 0; j < 4; j++) acc[i][j] = fmaf(av[i], bv[j], acc[i][j]);
    }
    __syncthreads();

    float* __restrict__ WhG = S.Wh;
    #pragma unroll
    for (int i = 0; i < 4; i++) {
        const int r = tr + 16 * i;
        #pragma unroll
        for (int j = 0; j < 4; j++) {
            const int c = tc + 16 * j;
            sW[r * 65 + c] = acc[i][j];
            WhG[((size_t)head * NN + (n0 + r)) * HIDC + c] = acc[i][j];
        }
    }
    __syncthreads();

    if (t < 64) {
        const int r = t;
        const float* ap1 = a1 + head * HIDC;
        const float* ap2 = a2 + head * HIDC;
        float v1 = 0.f, v2 = 0.f;
        #pragma unroll
        for (int c = 0; c < 64; c++) {
            const float w = sW[r * 65 + c];
            v1 = fmaf(w, ap1[c], v1);
            v2 = fmaf(w, ap2[c], v2);
        }
        S.s1[head * NN + n0 + r] = v1;
        S.s2[head * NN + n0 + r] = v2;
    }
}

// ---------------------------------------------------------------------------
// Kernel 2: hcat @ W_out + s1o/s2o.  grid 256, block 256
// ---------------------------------------------------------------------------
__global__ void k_gemm2(const float* __restrict__ Wo,
                        const float* __restrict__ a1,
                        const float* __restrict__ a2)
{
    __shared__ float sW[256 * 17];
    __shared__ float sh2[16 * 257];
    __shared__ float sAcc[16 * 17];

    const float* __restrict__ hcat = S.hcat;
    const int row0 = blockIdx.x * 16;
    const int t    = threadIdx.x;

    for (int idx = t; idx < 4096; idx += 256)
        sW[(idx >> 4) * 17 + (idx & 15)] = Wo[idx];
    #pragma unroll
    for (int r = 0; r < 16; r++)
        sh2[r * 257 + t] = hcat[(size_t)(row0 + r) * 256 + t];
    __syncthreads();

    const int tc = t & 15, tr = t >> 4;
    float acc = 0.f;
    #pragma unroll 8
    for (int k = 0; k < 256; k++)
        acc = fmaf(sh2[tr * 257 + k], sW[k * 17 + tc], acc);

    S.Wh2[(row0 + tr) * TT + tc] = acc;
    sAcc[tr * 17 + tc] = acc;
    __syncthreads();

    if (t < 16) {
        const int r = t;
        float v1 = 0.f, v2 = 0.f;
        #pragma unroll
        for (int c = 0; c < 16; c++) {
            const float w = sAcc[r * 17 + c];
            v1 = fmaf(w, a1[c], v1);
            v2 = fmaf(w, a2[c], v2);
        }
        S.s1o[row0 + r] = v1;
        S.s2o[row0 + r] = v2;
    }
}

// ---------------------------------------------------------------------------
// Kernel 3: bitonic sort (register/shuffle) + exp weights + fused fp64 scans
// 1 block of 1024 per head.
// ---------------------------------------------------------------------------
template<int L>
__global__ void k_sortscan()
{
    const float* __restrict__ s2  = (L == 0) ? S.s2  : S.s2o;
    float*       __restrict__ s2s = (L == 0) ? S.s2s : S.s2so;
    int*         __restrict__ perm= (L == 0) ? S.perm: S.permo;
    float*       __restrict__ A   = (L == 0) ? S.A   : S.Ao;
    float*       __restrict__ B   = (L == 0) ? S.B   : S.Bo;
    double*      __restrict__ sufAsc = ((L == 0) ? S.sufAsc : S.sufA2sc) + blockIdx.x * (NN + 1);
    double*      __restrict__ preBsc = ((L == 0) ? S.preBsc : S.preB2sc) + blockIdx.x * (NN + 1);

    __shared__ float key[NN];
    __shared__ int   sidx[NN];          // reused as double seg[2048] later

    const int base = blockIdx.x * NN;
    const int t    = threadIdx.x;
    const int lane = t & 31;

    float k0[4]; int x0[4];
    #pragma unroll
    for (int m = 0; m < 4; m++) {
        const int i = t + m * 1024;
        k0[m] = s2[base + i];
        x0[m] = i;
    }

    // stages k=2..32 entirely in registers (partner always in-warp)
    #pragma unroll
    for (int k = 2; k <= 32; k <<= 1) {
        #pragma unroll
        for (int j = k >> 1; j >= 1; j >>= 1) {
            #pragma unroll
            for (int m = 0; m < 4; m++) {
                const int i = t + m * 1024;
                const bool up = ((i & k) == 0);
                const float ok = __shfl_xor_sync(0xffffffffu, k0[m], j);
                const int   oi = __shfl_xor_sync(0xffffffffu, x0[m], j);
                const bool lower = ((lane & j) == 0);
                const bool wantMin = (lower == up);
                const bool take = wantMin ? (ok < k0[m]) : (ok > k0[m]);
                if (take) { k0[m] = ok; x0[m] = oi; }
            }
        }
    }
    #pragma unroll
    for (int m = 0; m < 4; m++) {
        const int i = t + m * 1024;
        key[i] = k0[m]; sidx[i] = x0[m];
    }
    __syncthreads();

    // stages k=64..4096: smem passes down to j=32, then in-warp shuffle tail
    for (int k = 64; k <= NN; k <<= 1) {
        for (int j = k >> 1; j >= 32; j >>= 1) {
            #pragma unroll
            for (int m = 0; m < 4; m++) {
                const int i = t + m * 1024;
                const int ixj = i ^ j;
                if (ixj > i) {
                    const bool up = ((i & k) == 0);
                    const float a = key[i], b = key[ixj];
                    if ((a > b) == up) {
                        key[i] = b; key[ixj] = a;
                        const int tmp = sidx[i]; sidx[i] = sidx[ixj]; sidx[ixj] = tmp;
                    }
                }
            }
            __syncthreads();
        }
        #pragma unroll
        for (int m = 0; m < 4; m++) {
            const int i = t + m * 1024;
            k0[m] = key[i]; x0[m] = sidx[i];
        }
        #pragma unroll
        for (int j = 16; j >= 1; j >>= 1) {
            #pragma unroll
            for (int m = 0; m < 4; m++) {
                const int i = t + m * 1024;
                const bool up = ((i & k) == 0);
                const float ok = __shfl_xor_sync(0xffffffffu, k0[m], j);
                const int   oi = __shfl_xor_sync(0xffffffffu, x0[m], j);
                const bool lower = ((lane & j) == 0);
                const bool wantMin = (lower == up);
                const bool take = wantMin ? (ok < k0[m]) : (ok > k0[m]);
                if (take) { k0[m] = ok; x0[m] = oi; }
            }
        }
        #pragma unroll
        for (int m = 0; m < 4; m++) {
            const int i = t + m * 1024;
            key[i] = k0[m]; sidx[i] = x0[m];
        }
        __syncthreads();
    }

    // write sorted keys / perm / exp weights from registers
    #pragma unroll
    for (int m = 0; m < 4; m++) {
        const int i = t + m * 1024;
        const float v = k0[m];
        s2s[base + i]  = v;
        perm[base + i] = x0[m];
        A[base + i]    = expf(v);
        B[base + i]    = expf(0.01f * v);
    }
    __syncthreads();

    // fused scalar scans (fp64): thread t owns positions 4t..4t+3
    double* seg = (double*)sidx;     // 2048 doubles
    float av[4], bv[4];
    double la = 0.0, lb = 0.0;
    #pragma unroll
    for (int e = 0; e < 4; e++) {
        const float v = key[4 * t + e];
        av[e] = expf(v); bv[e] = expf(0.01f * v);
        la += (double)av[e]; lb += (double)bv[e];
    }
    seg[t] = la; seg[1024 + t] = lb;
    __syncthreads();

    for (int d = 1; d < 1024; d <<= 1) {
        double va = 0.0, vb = 0.0;
        if (t >= d) { va = seg[t - d]; vb = seg[1024 + t - d]; }
        __syncthreads();
        seg[t] += va; seg[1024 + t] += vb;
        __syncthreads();
    }

    const double exA = seg[t] - la;
    const double exB = seg[1024 + t] - lb;
    const double totA = seg[1023];
    const double totB = seg[2047];

    double runB = exB, runA = exA;
    #pragma unroll
    for (int e = 0; e < 4; e++) {
        const int p = 4 * t + e;
        preBsc[p] = runB;        runB += (double)bv[e];
        sufAsc[p] = totA - runA; runA += (double)av[e];
    }
    if (t == 1023) { preBsc[NN] = totB; sufAsc[NN] = 0.0; }
}

// ---------------------------------------------------------------------------
// Kernel 4: per-chunk fp32 column sums of A*Wh[perm] and B*Wh[perm]
// ---------------------------------------------------------------------------
template<int C, int CPB, int L>
__global__ void k_chunksum()
{
    const int head = blockIdx.x;
    const float* __restrict__ Wh   = ((L == 0) ? S.Wh   : S.Wh2) + (size_t)head * NN * C;
    const int*   __restrict__ perm = ((L == 0) ? S.perm : S.permo) + head * NN;
    const float* __restrict__ A    = ((L == 0) ? S.A    : S.Ao)   + head * NN;
    const float* __restrict__ B    = ((L == 0) ? S.B    : S.Bo)   + head * NN;
    float*       __restrict__ csA  = ((L == 0) ? S.csA  : S.csA2) + (size_t)head * NCHUNK * C;
    float*       __restrict__ csB  = ((L == 0) ? S.csB  : S.csB2) + (size_t)head * NCHUNK * C;

    const int c = threadIdx.x % C;
    const int q = blockIdx.y * CPB + threadIdx.x / C;
    const int p0 = q * CHSZ;
    float sa = 0.f, sb = 0.f;
    #pragma unroll
    for (int e = 0; e < CHSZ; e++) {
        const int p = p0 + e;
        const float w = Wh[(size_t)perm[p] * C + c];
        sa = fmaf(A[p], w, sa);
        sb = fmaf(B[p], w, sb);
    }
    csA[q * C + c] = sa;
    csB[q * C + c] = sb;
}

// ---------------------------------------------------------------------------
// Kernel 5: scan of chunk sums — independent pipelined warp scans.
// Block = (head, group of 8 channels, A-or-B); 256 threads = 8 warps; warp w
// owns channel c0+w. Lane owns chunks q = lane + 32*i (i = 0..15), loaded from
// bank-conflict-free padded smem. The 16 warp scans are INDEPENDENT (no carry
// chain); round totals are combined in registers afterwards.
// blockIdx.z = 0 -> csB exclusive prefix; 1 -> csA exclusive suffix.
// ---------------------------------------------------------------------------
#define SCAN_G 8
template<int C, int L>
__global__ void k_chunkscan()
{
    __shared__ float sv[NCHUNK * 9];   // [q][9] padding: stride 9 coprime to 32

    const int head = blockIdx.x;
    const int c0   = blockIdx.y * SCAN_G;
    const bool doB = (blockIdx.z == 0);
    float* __restrict__ cs =
        (doB ? ((L == 0) ? S.csB : S.csB2) : ((L == 0) ? S.csA : S.csA2))
        + (size_t)head * NCHUNK * C;

    const int t    = threadIdx.x;
    const int lane = t & 31;
    const int w    = t >> 5;           // warp id = local channel

    // stage: 8 contiguous channels per q
    for (int idx = t; idx < NCHUNK * SCAN_G; idx += 256) {
        const int q  = idx >> 3;
        const int cl = idx & 7;
        sv[q * 9 + cl] = cs[q * C + c0 + cl];
    }
    __syncthreads();

    constexpr int R = NCHUNK / 32;     // 16 rounds per lane
    float vals[R], inc[R];
    #pragma unroll
    for (int i = 0; i < R; i++) {
        vals[i] = sv[(lane + 32 * i) * 9 + w];   // stride 9: conflict-free
        inc[i]  = vals[i];
    }

    // 16 independent inclusive warp scans, pipelined (no cross-round deps)
    #pragma unroll
    for (int d = 1; d < 32; d <<= 1) {
        #pragma unroll
        for (int i = 0; i < R; i++) {
            const float tv = __shfl_up_sync(0xffffffffu, inc[i], d);
            if (lane >= d) inc[i] += tv;
        }
    }
    float tot[R];
    #pragma unroll
    for (int i = 0; i < R; i++) tot[i] = __shfl_sync(0xffffffffu, inc[i], 31);

    // combine round totals locally (identical on all lanes)
    if (doB) {
        // exclusive prefix: rprefix(i) + (inc - val)
        float run = 0.f;
        #pragma unroll
        for (int i = 0; i < R; i++) {
            sv[(lane + 32 * i) * 9 + w] = run + (inc[i] - vals[i]);
            run += tot[i];
        }
    } else {
        // exclusive suffix: rsuffix(i) + (tot - inc)
        float run = 0.f;
        #pragma unroll
        for (int i = R - 1; i >= 0; i--) {
            sv[(lane + 32 * i) * 9 + w] = run + (tot[i] - inc[i]);
            run += tot[i];
        }
    }
    __syncthreads();

    for (int idx = t; idx < NCHUNK * SCAN_G; idx += 256) {
        const int q  = idx >> 3;
        const int cl = idx & 7;
        cs[q * C + c0 + cl] = sv[q * 9 + cl];
    }
}

// ---------------------------------------------------------------------------
// Kernel 6: per-row combine; row-level scalars computed once per row and
// shared via smem.  block 256 = IPB rows x C channels.
// ---------------------------------------------------------------------------
template<int C, bool DO_ELU, int L>
__global__ void k_combine(float* __restrict__ extOut, int rowStride)
{
    constexpr int IPB = 256 / C;
    __shared__ int    skk[IPB];
    __shared__ float  sEa[IPB], sEb[IPB], sWii[IPB];
    __shared__ double sRd[IPB];

    const int head = blockIdx.y;
    const float*  __restrict__ s1     = ((L == 0) ? S.s1     : S.s1o)  + head * NN;
    const float*  __restrict__ s2     = ((L == 0) ? S.s2     : S.s2o)  + head * NN;
    const float*  __restrict__ s2s    = ((L == 0) ? S.s2s    : S.s2so) + head * NN;
    const int*    __restrict__ perm   = ((L == 0) ? S.perm   : S.permo) + head * NN;
    const float*  __restrict__ A      = ((L == 0) ? S.A      : S.Ao)   + head * NN;
    const float*  __restrict__ B      = ((L == 0) ? S.B      : S.Bo)   + head * NN;
    const float*  __restrict__ Wh     = ((L == 0) ? S.Wh     : S.Wh2)  + (size_t)head * NN * C;
    const float*  __restrict__ csAs   = ((L == 0) ? S.csA    : S.csA2) + (size_t)head * NCHUNK * C;
    const float*  __restrict__ csBs   = ((L == 0) ? S.csB    : S.csB2) + (size_t)head * NCHUNK * C;
    const double* __restrict__ sufAsc = ((L == 0) ? S.sufAsc : S.sufA2sc) + head * (NN + 1);
    const double* __restrict__ preBsc = ((L == 0) ? S.preBsc : S.preB2sc) + head * (NN + 1);
    float* __restrict__ out = (L == 0) ? S.hcat : extOut;

    const int r = threadIdx.x / C;
    const int i = blockIdx.x * IPB + r;
    const int c = threadIdx.x % C;

    if (c == 0) {
        const float s1v = s1[i];
        const float ea  = expf(s1v);
        const float eb  = expf(0.01f * s1v);
        const float target = -s1v;
        int lo = 0, hi = NN;
        while (lo < hi) {
            const int mid = (lo + hi) >> 1;
            if (s2s[mid] < target) lo = mid + 1; else hi = mid;
        }
        const float tii = s1v + s2[i];
        const float wii = expf(tii >= 0.f ? tii : 0.01f * tii);
        const double denom = (double)ea * sufAsc[lo] + (double)eb * preBsc[lo] - (double)wii;
        skk[r] = lo;  sEa[r] = ea;  sEb[r] = eb;  sWii[r] = wii;
        sRd[r] = 1.0 / denom;
    }
    __syncthreads();

    const int   k   = skk[r];
    const float ea  = sEa[r];
    const float eb  = sEb[r];
    const float wii = sWii[r];
    const double rd = sRd[r];
    const int q = min(k >> CHLOG, NCHUNK - 1);

    float accA = csAs[q * C + c];     // sum over chunks > q (A-weighted)
    float accB = csBs[q * C + c];     // sum over chunks < q (B-weighted)

    const int p0 = q << CHLOG;
    #pragma unroll
    for (int e = 0; e < CHSZ; e++) {
        const int p = p0 + e;
        const float w = Wh[(size_t)perm[p] * C + c];
        if (p >= k) accA = fmaf(A[p], w, accA);
        else        accB = fmaf(B[p], w, accB);
    }

    const float num = ea * accA + eb * accB - wii * Wh[(size_t)i * C + c];
    float v = (float)((double)num * rd);
    if (DO_ELU) v = (v > 0.f) ? v : expm1f(v);

    out[(size_t)i * rowStride + head * C + c] = v;
}

// ---------------------------------------------------------------------------
// launch — kernel launches only (10 launches)
// ---------------------------------------------------------------------------
extern "C" void kernel_launch(void* const* d_in, const int* in_sizes, int n_in,
                              void* d_out, int out_size)
{
    const float* x       = (const float*)d_in[0];
    const float* W_heads = (const float*)d_in[3];
    const float* a1h     = (const float*)d_in[4];
    const float* a2h     = (const float*)d_in[5];
    const float* W_out   = (const float*)d_in[6];
    const float* a1o     = (const float*)d_in[7];
    const float* a2o     = (const float*)d_in[8];
    float* out = (float*)d_out;

    // ---- layer 1 (4 heads) ----
    k_gemm1<<<dim3(NN / 64, NH), 256>>>(x, W_heads, a1h, a2h);
    k_sortscan<0><<<NH, 1024>>>();
    k_chunksum<HIDC, 4, 0><<<dim3(NH, NCHUNK / 4), 256>>>();
    k_chunkscan<HIDC, 0><<<dim3(NH, HIDC / SCAN_G, 2), 256>>>();
    k_combine<HIDC, true, 0><<<dim3(NN / 4, NH), 256>>>(nullptr, NH * HIDC);

    // ---- layer 2 (output) ----
    k_gemm2<<<NN / 16, 256>>>(W_out, a1o, a2o);
    k_sortscan<1><<<1, 1024>>>();
    k_chunksum<TT, 16, 1><<<dim3(1, NCHUNK / 16), 256>>>();
    k_chunkscan<TT, 1><<<dim3(1, TT / SCAN_G, 2), 256>>>();
    k_combine<TT, false, 1><<<dim3(NN / 16, 1), 256>>>(out, TT);
}